// round 13
// baseline (speedup 1.0000x reference)
#include <cuda_runtime.h>
#include <cuda_bf16.h>
#include <math.h>

#define NN 100000
#define NE 1600000
#define FF 128
#define KK 8
#define MM 8
#define KM 64
#define EPSREL 0.05f
#define INV_N 1e-5f

#define NB 148                 /* persistent grid blocks */
#define NPB 676                /* nodes per block */
#define NSPLIT 352             /* nodes held in shared memory */
#define SMEM_DYN (NSPLIT*128)  /* 45056 bytes */
#define NEB ((NE + 1023)/1024)
#define NMF ((NN + 127)/128)
#define NZB ((NN + 1023)/1024)
#define NSPX ((NN + 7)/8)
#define NSC 98

// ------------------ static scratch (no allocations) ------------------
__device__ __align__(128) float g_Mfeat[(size_t)NN*KM];
__device__ __align__(128) __nv_bfloat16 g_Ub[(size_t)NN*KM];  // u (bf16), 2nd half
__device__ __align__(128) __nv_bfloat16 g_AU[(size_t)NN*KM];  // a*u (bf16)
__device__ __align__(128) float g_CT[(size_t)NN*KM];          // spmm out / cost (fp32)
__device__ __align__(128) float g_xsq[NN];
__device__ __align__(128) float g_P0[NB*KM];
__device__ __align__(128) float g_P1[NB*KM];
__device__ __align__(128) float g_Pabs[NB*KK];
__device__ __align__(128) double g_Fpart[NB*16];
__device__ __align__(128) int   g_deg[NN];
__device__ __align__(128) int   g_rowptr[NN+1];
__device__ __align__(128) int   g_cursor[NN];
__device__ __align__(128) int   g_csrdst[NE];
__device__ __align__(128) int   g_bsum[NSC];
__device__ __align__(128) int   g_boff[NSC];
__device__ float g_q[KM];
__device__ float g_tsqq[KM];
__device__ float g_tq2[KM];
__device__ float g_tfsq[KM];
__device__ float g_alpha[1];
__device__ unsigned g_cnt;

// ---- lightweight release/acquire grid barrier (single counter, R6-proven) ----
__device__ __forceinline__ void gridbar(int &gen){
    __syncthreads();
    if (threadIdx.x == 0){
        unsigned tgt = (unsigned)(gen + 1) * (unsigned)NB;
        asm volatile("red.release.gpu.global.add.u32 [%0], %1;"
                     :: "l"(&g_cnt), "r"(1u) : "memory");
        unsigned v;
        do {
            asm volatile("ld.acquire.gpu.global.u32 %0, [%1];"
                         : "=r"(v) : "l"(&g_cnt) : "memory");
        } while (v < tgt);
    }
    gen++;
    __syncthreads();
}

// ------------------ small precompute (+ counter reset) ------------------
__global__ void k_small(const float* __restrict__ q0, const float* __restrict__ tmpl,
                        const float* __restrict__ tf, const float* __restrict__ a0){
    __shared__ float sq[KM];
    int t = threadIdx.x;  // 64 threads
    if (t == 0) g_cnt = 0u;
    if (t < KM){
        float s = 0.f;
        #pragma unroll 8
        for (int f = 0; f < FF; f++){ float v = tf[t*FF+f]; s = fmaf(v, v, s); }
        g_tfsq[t] = s;
    }
    if (t == 0) g_alpha[0] = 1.f/(1.f + expf(-a0[0]));
    if (t < KK){
        int k = t;
        float mx = -1e30f;
        for (int j = 0; j < MM; j++) mx = fmaxf(mx, q0[k*MM+j]);
        float e[MM]; float s = 0.f;
        for (int j = 0; j < MM; j++){ e[j] = expf(q0[k*MM+j]-mx); s += e[j]; }
        for (int j = 0; j < MM; j++) sq[k*MM+j] = e[j]/s;
    }
    __syncthreads();
    if (t < KM){
        int k = t >> 3, i = t & 7;
        float s = 0.f, s2 = 0.f;
        #pragma unroll
        for (int j = 0; j < MM; j++){
            float tv = tmpl[k*64 + i*8 + j];
            float qv = sq[k*8 + j];
            s  = fmaf(tv*tv, qv, s);
            s2 = fmaf(tv,    qv, s2);
        }
        g_tsqq[t] = s;
        g_tq2[t]  = 2.f*s2;
        g_q[t]    = sq[t];
    }
}

// ------------------ CSR build ------------------
__global__ void k_zero(){
    int i = blockIdx.x*1024 + threadIdx.x;
    if (i < NN) g_deg[i] = 0;
}
__global__ void k_hist(const int* __restrict__ src){
    int e = blockIdx.x*1024 + threadIdx.x;
    if (e < NE) atomicAdd(&g_deg[src[e]], 1);
}
__global__ __launch_bounds__(1024) void k_scan1(){
    __shared__ int ss[1024];
    int t = threadIdx.x;
    int idx = blockIdx.x*1024 + t;
    int v = (idx < NN) ? g_deg[idx] : 0;
    ss[t] = v;
    __syncthreads();
    #pragma unroll
    for (int off = 1; off < 1024; off <<= 1){
        int x = (t >= off) ? ss[t-off] : 0;
        __syncthreads();
        ss[t] += x;
        __syncthreads();
    }
    if (idx < NN) g_rowptr[idx] = ss[t] - v;
    if (t == 1023) g_bsum[blockIdx.x] = ss[t];
}
__global__ void k_scan2(){
    __shared__ int ss[128];
    int t = threadIdx.x;
    int v = (t < NSC) ? g_bsum[t] : 0;
    ss[t] = v;
    __syncthreads();
    #pragma unroll
    for (int off = 1; off < 128; off <<= 1){
        int x = (t >= off) ? ss[t-off] : 0;
        __syncthreads();
        ss[t] += x;
        __syncthreads();
    }
    if (t < NSC) g_boff[t] = ss[t] - v;
    if (t == 0) g_rowptr[NN] = NE;
}
__global__ void k_scan3(){
    int idx = blockIdx.x*1024 + threadIdx.x;
    if (idx < NN){
        int r = g_rowptr[idx] + g_boff[blockIdx.x];
        g_rowptr[idx] = r;
        g_cursor[idx] = r;
    }
}
__global__ void k_fill(const int* __restrict__ src, const int* __restrict__ dst){
    int e = blockIdx.x*1024 + threadIdx.x;
    if (e < NE){
        int s = src[e];
        int pos = atomicAdd(&g_cursor[s], 1);
        g_csrdst[pos] = dst[e];
    }
}

// ------------------ |x|^2 per node ------------------
__global__ __launch_bounds__(256) void k_xsq(const float* __restrict__ x){
    int w = (blockIdx.x*256 + threadIdx.x) >> 5;
    int lane = threadIdx.x & 31;
    if (w >= NN) return;
    float4 v = *(const float4*)&x[(size_t)w*FF + lane*4];
    float s = v.x*v.x + v.y*v.y + v.z*v.z + v.w*v.w;
    #pragma unroll
    for (int o = 16; o > 0; o >>= 1) s += __shfl_down_sync(0xffffffffu, s, o);
    if (lane == 0) g_xsq[w] = s;
}

// ------------------ Mfeat GEMM ------------------
__global__ __launch_bounds__(128) void k_mfeat(const float* __restrict__ x,
                                               const float* __restrict__ tf){
    __shared__ float xs[16][132];
    __shared__ float ts[16][68];
    int tid = threadIdx.x;
    int n0 = blockIdx.x * 128;
    int ty = tid >> 3, tx = tid & 7;
    float acc[8][8];
    #pragma unroll
    for (int i = 0; i < 8; i++)
        #pragma unroll
        for (int j = 0; j < 8; j++) acc[i][j] = 0.f;
    int q = tid & 3, r0 = tid >> 2;
    int rt = tid >> 1, qt = (tid & 1) * 8;
    for (int kb = 0; kb < FF; kb += 16){
        #pragma unroll
        for (int itr = 0; itr < 4; itr++){
            int r = r0 + itr*32;
            int n = n0 + r;
            float4 v = make_float4(0.f,0.f,0.f,0.f);
            if (n < NN) v = *(const float4*)&x[(size_t)n*FF + kb + q*4];
            xs[q*4+0][r] = v.x; xs[q*4+1][r] = v.y;
            xs[q*4+2][r] = v.z; xs[q*4+3][r] = v.w;
        }
        {
            float4 a = *(const float4*)&tf[(size_t)rt*FF + kb + qt];
            float4 b = *(const float4*)&tf[(size_t)rt*FF + kb + qt + 4];
            ts[qt+0][rt] = a.x; ts[qt+1][rt] = a.y; ts[qt+2][rt] = a.z; ts[qt+3][rt] = a.w;
            ts[qt+4][rt] = b.x; ts[qt+5][rt] = b.y; ts[qt+6][rt] = b.z; ts[qt+7][rt] = b.w;
        }
        __syncthreads();
        #pragma unroll
        for (int kk = 0; kk < 16; kk++){
            float4 A0 = *(const float4*)&xs[kk][ty*8];
            float4 A1 = *(const float4*)&xs[kk][ty*8+4];
            float4 B0 = *(const float4*)&ts[kk][tx*8];
            float4 B1 = *(const float4*)&ts[kk][tx*8+4];
            float av[8] = {A0.x,A0.y,A0.z,A0.w,A1.x,A1.y,A1.z,A1.w};
            float bv[8] = {B0.x,B0.y,B0.z,B0.w,B1.x,B1.y,B1.z,B1.w};
            #pragma unroll
            for (int i = 0; i < 8; i++)
                #pragma unroll
                for (int j = 0; j < 8; j++)
                    acc[i][j] = fmaf(av[i], bv[j], acc[i][j]);
        }
        __syncthreads();
    }
    #pragma unroll
    for (int i = 0; i < 8; i++){
        int n = n0 + ty*8 + i;
        if (n < NN){
            float xq = g_xsq[n];
            int c = tx*8;
            float4 o0, o1;
            o0.x = xq + g_tfsq[c+0] - 2.f*acc[i][0];
            o0.y = xq + g_tfsq[c+1] - 2.f*acc[i][1];
            o0.z = xq + g_tfsq[c+2] - 2.f*acc[i][2];
            o0.w = xq + g_tfsq[c+3] - 2.f*acc[i][3];
            o1.x = xq + g_tfsq[c+4] - 2.f*acc[i][4];
            o1.y = xq + g_tfsq[c+5] - 2.f*acc[i][5];
            o1.z = xq + g_tfsq[c+6] - 2.f*acc[i][6];
            o1.w = xq + g_tfsq[c+7] - 2.f*acc[i][7];
            *(float4*)&g_Mfeat[(size_t)n*KM + c]     = o0;
            *(float4*)&g_Mfeat[(size_t)n*KM + c + 4] = o1;
        }
    }
}

// ------------------ column-sum partial reduce helper ------------------
__device__ __forceinline__ void colreduce(float* c, float* buf, int tid, float* dst){
    unsigned full = 0xffffffffu;
    #pragma unroll
    for (int j = 0; j < 8; j++){
        c[j] += __shfl_down_sync(full, c[j], 16);
        c[j] += __shfl_down_sync(full, c[j], 8);
    }
    int lane = tid & 31, wp = tid >> 5;
    if (lane < 8){
        #pragma unroll
        for (int j = 0; j < 8; j++) buf[j*256 + wp*8 + lane] = c[j];
    }
    __syncthreads();
    if (tid < 64){
        int j = tid >> 3, kk = tid & 7;
        float s = 0.f;
        #pragma unroll
        for (int w = 0; w < 32; w++) s += buf[j*256 + w*8 + kk];
        __stcg(&dst[kk*8 + j], s);
    }
}

// ---- spmm: CTraw[r][c] = sum_{d in row r} AU[d][c], BLOCK-OWN rows ----
__device__ __forceinline__ void spmm_phase(int B0, int B1, int tid){
    int lane = tid & 31;
    int c2 = lane*2;
    for (int r = B0 + (tid >> 5); r < B1; r += 32){
        int beg = g_rowptr[r], end = g_rowptr[r+1];
        float ax = 0.f, ay = 0.f;
        #pragma unroll 4
        for (int e = beg; e < end; e++){
            int d = g_csrdst[e];
            unsigned uraw = __ldcg((const unsigned*)&g_AU[(size_t)d*KM + c2]);
            float2 u = __bfloat1622float2(*(__nv_bfloat162*)&uraw);
            ax += u.x;
            ay += u.y;
        }
        float2 o = make_float2(ax, ay);
        *(float2*)&g_CT[(size_t)r*KM + c2] = o;
    }
}

// ---- sink accumulate step from a raw bf16x8 octet ----
__device__ __forceinline__ void sink_step(uint4 raw,
    float b0, float b1, float b2, float b3,
    float b4, float b5, float b6, float b7, float* c){
    float2 u0 = __bfloat1622float2(*(__nv_bfloat162*)&raw.x);
    float2 u1 = __bfloat1622float2(*(__nv_bfloat162*)&raw.y);
    float2 u2 = __bfloat1622float2(*(__nv_bfloat162*)&raw.z);
    float2 u3 = __bfloat1622float2(*(__nv_bfloat162*)&raw.w);
    float s = b0*u0.x; s = fmaf(b1,u0.y,s);
    s = fmaf(b2,u1.x,s); s = fmaf(b3,u1.y,s);
    s = fmaf(b4,u2.x,s); s = fmaf(b5,u2.y,s);
    s = fmaf(b6,u3.x,s); s = fmaf(b7,u3.y,s);
    float a = __fdividef(INV_N, s);
    c[0]=fmaf(a,u0.x,c[0]); c[1]=fmaf(a,u0.y,c[1]);
    c[2]=fmaf(a,u1.x,c[2]); c[3]=fmaf(a,u1.y,c[3]);
    c[4]=fmaf(a,u2.x,c[4]); c[5]=fmaf(a,u2.y,c[5]);
    c[6]=fmaf(a,u3.x,c[6]); c[7]=fmaf(a,u3.y,c[7]);
}
__device__ __forceinline__ void au_step(uint4 raw,
    float b0, float b1, float b2, float b3,
    float b4, float b5, float b6, float b7, uint4* dst){
    float2 u0 = __bfloat1622float2(*(__nv_bfloat162*)&raw.x);
    float2 u1 = __bfloat1622float2(*(__nv_bfloat162*)&raw.y);
    float2 u2 = __bfloat1622float2(*(__nv_bfloat162*)&raw.z);
    float2 u3 = __bfloat1622float2(*(__nv_bfloat162*)&raw.w);
    float s = b0*u0.x; s = fmaf(b1,u0.y,s);
    s = fmaf(b2,u1.x,s); s = fmaf(b3,u1.y,s);
    s = fmaf(b4,u2.x,s); s = fmaf(b5,u2.y,s);
    s = fmaf(b6,u3.x,s); s = fmaf(b7,u3.y,s);
    float a = __fdividef(INV_N, s);
    __nv_bfloat162 q0 = __floats2bfloat162_rn(a*u0.x, a*u0.y);
    __nv_bfloat162 q1 = __floats2bfloat162_rn(a*u1.x, a*u1.y);
    __nv_bfloat162 q2 = __floats2bfloat162_rn(a*u2.x, a*u2.y);
    __nv_bfloat162 q3 = __floats2bfloat162_rn(a*u3.x, a*u3.y);
    uint4 aw;
    aw.x = *(unsigned*)&q0; aw.y = *(unsigned*)&q1;
    aw.z = *(unsigned*)&q2; aw.w = *(unsigned*)&q3;
    *dst = aw;
}

// ------------------ the big persistent kernel ------------------
__global__ __launch_bounds__(1024, 1) void k_main(const float* __restrict__ tmpl,
                                                  float* __restrict__ out){
    extern __shared__ __align__(16) uint4 su[];   // NSPLIT*8 uint4 (45 KB)
    __shared__ __align__(16) float buf[2048];
    __shared__ float stb[512];
    __shared__ float stsq[64];
    __shared__ float sq[64];
    __shared__ float sb[64];
    __shared__ float sie[8];
    int tid = threadIdx.x;
    int bid = blockIdx.x;
    int gen = 0;
    const float al = g_alpha[0];
    const float om = 1.f - al;

    if (tid < 64){
        sq[tid] = g_q[tid];
        int p = tid >> 3, k2 = tid & 7;
        stsq[p*8 + k2] = g_tsqq[k2*8 + p];
    }

    const int B0 = bid * NPB;
    const int B1 = (B0 + NPB < NN) ? (B0 + NPB) : NN;
    const int BS = B0 + NSPLIT;            // smem/global split point (< B1 always)
    const int k = tid & 7;
    const int nofs = tid >> 3;             // 0..127

    for (int t = 0; t < 5; t++){
        // ---- spmm phase (t>0): block-own rows ----
        if (t > 0) spmm_phase(B0, B1, tid);
        // ---- cost phase ----
        if (t == 0){
            if (tid < 64){ int p = tid >> 3, k2 = tid & 7; stb[p*8+k2] = g_tq2[k2*8+p]; }
        } else {
            if (tid < 512){
                int p = tid >> 6, m = (tid >> 3) & 7, k2 = tid & 7;
                stb[tid] = 2.f * sb[k2*8+m] * tmpl[k2*64 + p*8 + m];
            }
        }
        __syncthreads();
        float cabs = 0.f;
        for (int n = B0 + nofs; n < B1; n += 128){
            float d = (float)g_deg[n] * INV_N;
            const float4* mp = (const float4*)&g_Mfeat[(size_t)n*KM + k*8];
            float4 m0 = mp[0], m1 = mp[1];
            float mf[8] = {m0.x,m0.y,m0.z,m0.w,m1.x,m1.y,m1.z,m1.w};
            float cc[8];
            if (t == 0){
                #pragma unroll
                for (int p = 0; p < 8; p++)
                    cc[p] = d + stsq[p*8+k] - d*stb[p*8+k];
            } else {
                const float4* cp0 = (const float4*)&g_CT[(size_t)n*KM + k*8];
                float4 t0 = cp0[0], t1 = cp0[1];
                float ct[8] = {t0.x,t0.y,t0.z,t0.w,t1.x,t1.y,t1.z,t1.w};
                #pragma unroll
                for (int p = 0; p < 8; p++){
                    float s = 0.f;
                    #pragma unroll
                    for (int m = 0; m < 8; m++)
                        s = fmaf(ct[m], stb[p*64 + m*8 + k], s);
                    cc[p] = d + stsq[p*8+k] - s;
                }
            }
            #pragma unroll
            for (int p = 0; p < 8; p++){
                cc[p] = al*cc[p] + om*mf[p];
                cabs += fabsf(cc[p]);
            }
            float4 o0 = make_float4(cc[0],cc[1],cc[2],cc[3]);
            float4 o1 = make_float4(cc[4],cc[5],cc[6],cc[7]);
            float4* cp = (float4*)&g_CT[(size_t)n*KM + k*8];
            cp[0] = o0; cp[1] = o1;
        }
        {
            unsigned full = 0xffffffffu;
            cabs += __shfl_down_sync(full, cabs, 16);
            cabs += __shfl_down_sync(full, cabs, 8);
            int lane = tid & 31, wp = tid >> 5;
            if (lane < 8) buf[wp*8 + lane] = cabs;
            __syncthreads();
            if (tid < 8){
                float s = 0.f;
                #pragma unroll
                for (int w = 0; w < 32; w++) s += buf[w*8 + tid];
                __stcg(&g_Pabs[bid*8 + tid], s);
            }
        }
        gridbar(gen);
        // ---- eps + exp init phase ----
        if (tid < 256){
            int kk = tid & 7, r = tid >> 3;
            float s = 0.f;
            for (int i = r; i < NB; i += 32) s += __ldcg(&g_Pabs[i*8 + kk]);
            buf[tid] = s;
        }
        __syncthreads();
        if (tid < 8){
            float s = 0.f;
            #pragma unroll
            for (int r = 0; r < 32; r++) s += buf[r*8 + tid];
            sie[tid] = (float)(NN*MM) / (EPSREL * s);
        }
        __syncthreads();
        const float ie = sie[k];
        float c[8];
        #pragma unroll
        for (int j = 0; j < 8; j++) c[j] = 0.f;
        for (int n = B0 + nofs; n < B1; n += 128){
            const float4* cp = (const float4*)&g_CT[(size_t)n*KM + k*8];
            float4 c0 = cp[0], c1 = cp[1];
            float u0 = __expf(-c0.x*ie), u1 = __expf(-c0.y*ie);
            float u2 = __expf(-c0.z*ie), u3 = __expf(-c0.w*ie);
            float u4 = __expf(-c1.x*ie), u5 = __expf(-c1.y*ie);
            float u6 = __expf(-c1.z*ie), u7 = __expf(-c1.w*ie);
            __nv_bfloat162 p0 = __floats2bfloat162_rn(u0,u1);
            __nv_bfloat162 p1 = __floats2bfloat162_rn(u2,u3);
            __nv_bfloat162 p2 = __floats2bfloat162_rn(u4,u5);
            __nv_bfloat162 p3 = __floats2bfloat162_rn(u6,u7);
            uint4 raw;
            raw.x = *(unsigned*)&p0; raw.y = *(unsigned*)&p1;
            raw.z = *(unsigned*)&p2; raw.w = *(unsigned*)&p3;
            if (n < BS) su[(n - B0)*8 + k] = raw;
            else        *(uint4*)&g_Ub[(size_t)n*KM + k*8] = raw;
            float2 v0 = __bfloat1622float2(p0);
            float2 v1 = __bfloat1622float2(p1);
            float2 v2 = __bfloat1622float2(p2);
            float2 v3 = __bfloat1622float2(p3);
            c[0]+=v0.x; c[1]+=v0.y; c[2]+=v1.x; c[3]+=v1.y;
            c[4]+=v2.x; c[5]+=v2.y; c[6]+=v3.x; c[7]+=v3.y;
        }
        colreduce(c, buf, tid, &g_P0[bid*64]);
        gridbar(gen);
        // ---- 20 Sinkhorn iterations (U: smem half + global half) ----
        for (int it = 0; it < 20; it++){
            const float* Pp = (it & 1) ? g_P1 : g_P0;
            float* Pn = (it & 1) ? g_P0 : g_P1;
            if (tid < 512){
                int km = tid & 63, r = tid >> 6;
                float s = 0.f;
                #pragma unroll 4
                for (int i = r; i < NB; i += 8) s += __ldcg(&Pp[i*64 + km]);
                buf[tid] = s;
            }
            __syncthreads();
            if (tid < 64){
                float s = 0.f;
                #pragma unroll
                for (int r = 0; r < 8; r++) s += buf[r*64 + tid];
                sb[tid] = __fdividef(sq[tid], s);
            }
            __syncthreads();
            float b0 = sb[k*8+0], b1 = sb[k*8+1], b2 = sb[k*8+2], b3 = sb[k*8+3];
            float b4 = sb[k*8+4], b5 = sb[k*8+5], b6 = sb[k*8+6], b7 = sb[k*8+7];
            if (it < 19){
                #pragma unroll
                for (int j = 0; j < 8; j++) c[j] = 0.f;
                // smem half (LDS pipe)
                for (int n = B0 + nofs; n < BS; n += 128){
                    uint4 raw = su[(n - B0)*8 + k];
                    sink_step(raw, b0,b1,b2,b3,b4,b5,b6,b7, c);
                }
                // global half (LDG pipe)
                for (int n = BS + nofs; n < B1; n += 128){
                    uint4 raw = *(const uint4*)&g_Ub[(size_t)n*KM + k*8];
                    sink_step(raw, b0,b1,b2,b3,b4,b5,b6,b7, c);
                }
                colreduce(c, buf, tid, &Pn[bid*64]);
                gridbar(gen);
            } else {
                for (int n = B0 + nofs; n < BS; n += 128){
                    uint4 raw = su[(n - B0)*8 + k];
                    au_step(raw, b0,b1,b2,b3,b4,b5,b6,b7,
                            (uint4*)&g_AU[(size_t)n*KM + k*8]);
                }
                for (int n = BS + nofs; n < B1; n += 128){
                    uint4 raw = *(const uint4*)&g_Ub[(size_t)n*KM + k*8];
                    au_step(raw, b0,b1,b2,b3,b4,b5,b6,b7,
                            (uint4*)&g_AU[(size_t)n*KM + k*8]);
                }
            }
        }
        gridbar(gen);   // AU visible for next spmm (cross-block gather)
    }
    // ---- final spmm with converged AU (block-own rows, no barrier) ----
    spmm_phase(B0, B1, tid);
    // ---- fgw partials ----
    if (tid < 512){
        int p = tid >> 6, m = (tid >> 3) & 7, k2 = tid & 7;
        stb[tid] = 2.f * sb[k2*8+m] * tmpl[k2*64 + p*8 + m];
    }
    __syncthreads();
    {
        double s1 = 0.0, s2 = 0.0;
        for (int n = B0 + nofs; n < B1; n += 128){
            float d = (float)g_deg[n] * INV_N;
            uint4 raw = *(const uint4*)&g_AU[(size_t)n*KM + k*8];
            float2 v0 = __bfloat1622float2(*(__nv_bfloat162*)&raw.x);
            float2 v1 = __bfloat1622float2(*(__nv_bfloat162*)&raw.y);
            float2 v2 = __bfloat1622float2(*(__nv_bfloat162*)&raw.z);
            float2 v3 = __bfloat1622float2(*(__nv_bfloat162*)&raw.w);
            float au[8] = {v0.x,v0.y,v1.x,v1.y,v2.x,v2.y,v3.x,v3.y};
            const float4* mp = (const float4*)&g_Mfeat[(size_t)n*KM + k*8];
            float4 m0 = mp[0], m1 = mp[1];
            float mf[8] = {m0.x,m0.y,m0.z,m0.w,m1.x,m1.y,m1.z,m1.w};
            const float4* cp0 = (const float4*)&g_CT[(size_t)n*KM + k*8];
            float4 t0 = cp0[0], t1 = cp0[1];
            float ct[8] = {t0.x,t0.y,t0.z,t0.w,t1.x,t1.y,t1.z,t1.w};
            float accM = 0.f, accT = 0.f;
            #pragma unroll
            for (int p = 0; p < 8; p++){
                float T = au[p] * sb[k*8+p];
                float s = 0.f;
                #pragma unroll
                for (int m = 0; m < 8; m++)
                    s = fmaf(ct[m], stb[p*64 + m*8 + k], s);
                float tens = d + stsq[p*8+k] - s;
                accM = fmaf(mf[p], T, accM);
                accT = fmaf(tens,  T, accT);
            }
            s1 += (double)accM;
            s2 += (double)accT;
        }
        unsigned full = 0xffffffffu;
        s1 += __shfl_down_sync(full, s1, 16);
        s1 += __shfl_down_sync(full, s1, 8);
        s2 += __shfl_down_sync(full, s2, 16);
        s2 += __shfl_down_sync(full, s2, 8);
        double* dbuf = (double*)buf;
        int lane = tid & 31, wp = tid >> 5;
        if (lane < 8){
            dbuf[wp*8 + lane] = s1;
            dbuf[256 + wp*8 + lane] = s2;
        }
        __syncthreads();
        if (tid < 16){
            int which = tid >> 3, k2 = tid & 7;
            double s = 0.0;
            #pragma unroll
            for (int w = 0; w < 32; w++) s += dbuf[which*256 + w*8 + k2];
            g_Fpart[bid*16 + which*8 + k2] = s;
        }
    }
    gridbar(gen);
    // ---- final output (block 0) ----
    if (bid == 0 && tid < 8){
        double sA = 0.0, sB = 0.0;
        for (int i = 0; i < NB; i++){
            sA += __ldcg(&g_Fpart[i*16 + tid]);
            sB += __ldcg(&g_Fpart[i*16 + 8 + tid]);
        }
        double ald = (double)al;
        out[tid] = (float)((1.0 - ald)*sA + ald*sB);
    }
}

// ------------------ launch ------------------
extern "C" void kernel_launch(void* const* d_in, const int* in_sizes, int n_in,
                              void* d_out, int out_size){
    const float* x    = (const float*)d_in[0];
    const int*   ei   = (const int*)  d_in[1];
    const float* tmpl = (const float*)d_in[2];
    const float* tf   = (const float*)d_in[3];
    const float* q0   = (const float*)d_in[4];
    const float* a0   = (const float*)d_in[5];
    float* out = (float*)d_out;
    const int* src = ei;
    const int* dst = ei + NE;

    static int smem_set = 0;
    if (!smem_set){
        cudaFuncSetAttribute(k_main, cudaFuncAttributeMaxDynamicSharedMemorySize,
                             SMEM_DYN);
        smem_set = 1;
    }

    k_small<<<1, 64>>>(q0, tmpl, tf, a0);
    k_zero<<<NZB, 1024>>>();
    k_hist<<<NEB, 1024>>>(src);
    k_scan1<<<NSC, 1024>>>();
    k_scan2<<<1, 128>>>();
    k_scan3<<<NSC, 1024>>>();
    k_fill<<<NEB, 1024>>>(src, dst);
    k_xsq<<<NSPX, 256>>>(x);
    k_mfeat<<<NMF, 128>>>(x, tf);
    k_main<<<NB, 1024, SMEM_DYN>>>(tmpl, out);
}

// round 14
// speedup vs baseline: 1.0170x; 1.0170x over previous
#include <cuda_runtime.h>
#include <cuda_bf16.h>
#include <math.h>

#define NN 100000
#define NE 1600000
#define FF 128
#define KK 8
#define MM 8
#define KM 64
#define EPSREL 0.05f
#define INV_N 1e-5f

#define NB 148                 /* persistent grid blocks */
#define NPB 676                /* nodes per block */
#define NEB ((NE + 1023)/1024) /* 1563 */
#define NMF ((NN + 127)/128)   /* 782 */
#define NZB ((NN + 1023)/1024) /* 98  */
#define NSC 98

// ------------------ static scratch (no allocations) ------------------
__device__ __align__(128) float g_Mfeat[(size_t)NN*KM];
__device__ __align__(128) __nv_bfloat16 g_Ub[(size_t)NN*KM];  // u (bf16)
__device__ __align__(128) __nv_bfloat16 g_AU[(size_t)NN*KM];  // a*u (bf16)
__device__ __align__(128) float g_CT[(size_t)NN*KM];          // spmm out / cost (fp32)
__device__ __align__(128) float g_P0[NB*KM];
__device__ __align__(128) float g_P1[NB*KM];
__device__ __align__(128) float g_Pabs[NB*KK];
__device__ __align__(128) double g_Fpart[NB*16];
__device__ __align__(128) int   g_deg[NN];
__device__ __align__(128) int   g_rowptr[NN+1];
__device__ __align__(128) int   g_cursor[NN];
__device__ __align__(128) int   g_csrdst[NE];
__device__ __align__(128) int   g_bsum[NSC];
__device__ __align__(128) int   g_boff[NSC];
__device__ float g_q[KM];
__device__ float g_tsqq[KM];
__device__ float g_tq2[KM];
__device__ float g_tfsq[KM];
__device__ float g_alpha[1];
__device__ unsigned g_cnt;

// ---- lightweight release/acquire grid barrier (single counter, R6-proven) ----
__device__ __forceinline__ void gridbar(int &gen){
    __syncthreads();
    if (threadIdx.x == 0){
        unsigned tgt = (unsigned)(gen + 1) * (unsigned)NB;
        asm volatile("red.release.gpu.global.add.u32 [%0], %1;"
                     :: "l"(&g_cnt), "r"(1u) : "memory");
        unsigned v;
        do {
            asm volatile("ld.acquire.gpu.global.u32 %0, [%1];"
                         : "=r"(v) : "l"(&g_cnt) : "memory");
        } while (v < tgt);
    }
    gen++;
    __syncthreads();
}

// ------------------ small precompute (+ counter reset) ------------------
__global__ void k_small(const float* __restrict__ q0, const float* __restrict__ tmpl,
                        const float* __restrict__ tf, const float* __restrict__ a0){
    __shared__ float sq[KM];
    int t = threadIdx.x;  // 64 threads
    if (t == 0) g_cnt = 0u;
    if (t < KM){
        float s = 0.f;
        #pragma unroll 8
        for (int f = 0; f < FF; f++){ float v = tf[t*FF+f]; s = fmaf(v, v, s); }
        g_tfsq[t] = s;
    }
    if (t == 0) g_alpha[0] = 1.f/(1.f + expf(-a0[0]));
    if (t < KK){
        int k = t;
        float mx = -1e30f;
        for (int j = 0; j < MM; j++) mx = fmaxf(mx, q0[k*MM+j]);
        float e[MM]; float s = 0.f;
        for (int j = 0; j < MM; j++){ e[j] = expf(q0[k*MM+j]-mx); s += e[j]; }
        for (int j = 0; j < MM; j++) sq[k*MM+j] = e[j]/s;
    }
    __syncthreads();
    if (t < KM){
        int k = t >> 3, i = t & 7;
        float s = 0.f, s2 = 0.f;
        #pragma unroll
        for (int j = 0; j < MM; j++){
            float tv = tmpl[k*64 + i*8 + j];
            float qv = sq[k*8 + j];
            s  = fmaf(tv*tv, qv, s);
            s2 = fmaf(tv,    qv, s2);
        }
        g_tsqq[t] = s;
        g_tq2[t]  = 2.f*s2;
        g_q[t]    = sq[t];
    }
}

// ------------------ CSR build ------------------
__global__ void k_zero(){
    int i = blockIdx.x*1024 + threadIdx.x;
    if (i < NN) g_deg[i] = 0;
}
__global__ void k_hist(const int* __restrict__ src){
    int e = blockIdx.x*1024 + threadIdx.x;
    if (e < NE) atomicAdd(&g_deg[src[e]], 1);
}
__global__ __launch_bounds__(1024) void k_scan1(){
    __shared__ int ss[1024];
    int t = threadIdx.x;
    int idx = blockIdx.x*1024 + t;
    int v = (idx < NN) ? g_deg[idx] : 0;
    ss[t] = v;
    __syncthreads();
    #pragma unroll
    for (int off = 1; off < 1024; off <<= 1){
        int x = (t >= off) ? ss[t-off] : 0;
        __syncthreads();
        ss[t] += x;
        __syncthreads();
    }
    if (idx < NN) g_rowptr[idx] = ss[t] - v;
    if (t == 1023) g_bsum[blockIdx.x] = ss[t];
}
__global__ void k_scan2(){
    __shared__ int ss[128];
    int t = threadIdx.x;
    int v = (t < NSC) ? g_bsum[t] : 0;
    ss[t] = v;
    __syncthreads();
    #pragma unroll
    for (int off = 1; off < 128; off <<= 1){
        int x = (t >= off) ? ss[t-off] : 0;
        __syncthreads();
        ss[t] += x;
        __syncthreads();
    }
    if (t < NSC) g_boff[t] = ss[t] - v;
    if (t == 0) g_rowptr[NN] = NE;
}
__global__ void k_scan3(){
    int idx = blockIdx.x*1024 + threadIdx.x;
    if (idx < NN){
        int r = g_rowptr[idx] + g_boff[blockIdx.x];
        g_rowptr[idx] = r;
        g_cursor[idx] = r;
    }
}
__global__ void k_fill(const int* __restrict__ src, const int* __restrict__ dst){
    int e = blockIdx.x*1024 + threadIdx.x;
    if (e < NE){
        int s = src[e];
        int pos = atomicAdd(&g_cursor[s], 1);
        g_csrdst[pos] = dst[e];
    }
}

// ------------------ Mfeat GEMM (with fused |x|^2) ------------------
__global__ __launch_bounds__(128) void k_mfeat(const float* __restrict__ x,
                                               const float* __restrict__ tf){
    __shared__ float xs[16][132];
    __shared__ float ts[16][68];
    __shared__ float sxq[128];
    int tid = threadIdx.x;
    int n0 = blockIdx.x * 128;
    int ty = tid >> 3, tx = tid & 7;
    float acc[8][8];
    #pragma unroll
    for (int i = 0; i < 8; i++)
        #pragma unroll
        for (int j = 0; j < 8; j++) acc[i][j] = 0.f;
    int q = tid & 3, r0 = tid >> 2;
    int rt = tid >> 1, qt = (tid & 1) * 8;
    float xp[4] = {0.f, 0.f, 0.f, 0.f};
    for (int kb = 0; kb < FF; kb += 16){
        #pragma unroll
        for (int itr = 0; itr < 4; itr++){
            int r = r0 + itr*32;
            int n = n0 + r;
            float4 v = make_float4(0.f,0.f,0.f,0.f);
            if (n < NN) v = *(const float4*)&x[(size_t)n*FF + kb + q*4];
            xp[itr] = fmaf(v.x, v.x, xp[itr]);
            xp[itr] = fmaf(v.y, v.y, xp[itr]);
            xp[itr] = fmaf(v.z, v.z, xp[itr]);
            xp[itr] = fmaf(v.w, v.w, xp[itr]);
            xs[q*4+0][r] = v.x; xs[q*4+1][r] = v.y;
            xs[q*4+2][r] = v.z; xs[q*4+3][r] = v.w;
        }
        {
            float4 a = *(const float4*)&tf[(size_t)rt*FF + kb + qt];
            float4 b = *(const float4*)&tf[(size_t)rt*FF + kb + qt + 4];
            ts[qt+0][rt] = a.x; ts[qt+1][rt] = a.y; ts[qt+2][rt] = a.z; ts[qt+3][rt] = a.w;
            ts[qt+4][rt] = b.x; ts[qt+5][rt] = b.y; ts[qt+6][rt] = b.z; ts[qt+7][rt] = b.w;
        }
        __syncthreads();
        #pragma unroll
        for (int kk = 0; kk < 16; kk++){
            float4 A0 = *(const float4*)&xs[kk][ty*8];
            float4 A1 = *(const float4*)&xs[kk][ty*8+4];
            float4 B0 = *(const float4*)&ts[kk][tx*8];
            float4 B1 = *(const float4*)&ts[kk][tx*8+4];
            float av[8] = {A0.x,A0.y,A0.z,A0.w,A1.x,A1.y,A1.z,A1.w};
            float bv[8] = {B0.x,B0.y,B0.z,B0.w,B1.x,B1.y,B1.z,B1.w};
            #pragma unroll
            for (int i = 0; i < 8; i++)
                #pragma unroll
                for (int j = 0; j < 8; j++)
                    acc[i][j] = fmaf(av[i], bv[j], acc[i][j]);
        }
        __syncthreads();
    }
    // reduce |x|^2 partials across the 4 loader lanes per row
    #pragma unroll
    for (int itr = 0; itr < 4; itr++){
        float s = xp[itr];
        s += __shfl_xor_sync(0xffffffffu, s, 1);
        s += __shfl_xor_sync(0xffffffffu, s, 2);
        if (q == 0) sxq[r0 + itr*32] = s;
    }
    __syncthreads();
    #pragma unroll
    for (int i = 0; i < 8; i++){
        int n = n0 + ty*8 + i;
        if (n < NN){
            float xq = sxq[ty*8 + i];
            int c = tx*8;
            float4 o0, o1;
            o0.x = xq + g_tfsq[c+0] - 2.f*acc[i][0];
            o0.y = xq + g_tfsq[c+1] - 2.f*acc[i][1];
            o0.z = xq + g_tfsq[c+2] - 2.f*acc[i][2];
            o0.w = xq + g_tfsq[c+3] - 2.f*acc[i][3];
            o1.x = xq + g_tfsq[c+4] - 2.f*acc[i][4];
            o1.y = xq + g_tfsq[c+5] - 2.f*acc[i][5];
            o1.z = xq + g_tfsq[c+6] - 2.f*acc[i][6];
            o1.w = xq + g_tfsq[c+7] - 2.f*acc[i][7];
            *(float4*)&g_Mfeat[(size_t)n*KM + c]     = o0;
            *(float4*)&g_Mfeat[(size_t)n*KM + c + 4] = o1;
        }
    }
}

// ------------------ column-sum partial reduce helper ------------------
__device__ __forceinline__ void colreduce(float* c, float* buf, int tid, float* dst){
    unsigned full = 0xffffffffu;
    #pragma unroll
    for (int j = 0; j < 8; j++){
        c[j] += __shfl_down_sync(full, c[j], 16);
        c[j] += __shfl_down_sync(full, c[j], 8);
    }
    int lane = tid & 31, wp = tid >> 5;
    if (lane < 8){
        #pragma unroll
        for (int j = 0; j < 8; j++) buf[j*256 + wp*8 + lane] = c[j];
    }
    __syncthreads();
    if (tid < 64){
        int j = tid >> 3, kk = tid & 7;
        float s = 0.f;
        #pragma unroll
        for (int w = 0; w < 32; w++) s += buf[j*256 + w*8 + kk];
        __stcg(&dst[kk*8 + j], s);
    }
}

// ---- spmm: CTraw[r][c] = sum_{d in row r} AU[d][c], BLOCK-OWN rows ----
__device__ __forceinline__ void spmm_phase(int B0, int B1, int tid){
    int lane = tid & 31;
    int c2 = lane*2;
    for (int r = B0 + (tid >> 5); r < B1; r += 32){
        int beg = g_rowptr[r], end = g_rowptr[r+1];
        float ax = 0.f, ay = 0.f;
        #pragma unroll 4
        for (int e = beg; e < end; e++){
            int d = g_csrdst[e];
            unsigned uraw = __ldcg((const unsigned*)&g_AU[(size_t)d*KM + c2]);
            float2 u = __bfloat1622float2(*(__nv_bfloat162*)&uraw);
            ax += u.x;
            ay += u.y;
        }
        float2 o = make_float2(ax, ay);
        *(float2*)&g_CT[(size_t)r*KM + c2] = o;
    }
}

// ------------------ the big persistent kernel ------------------
__global__ __launch_bounds__(1024, 1) void k_main(const float* __restrict__ tmpl,
                                                  float* __restrict__ out){
    __shared__ __align__(16) float buf[2048];
    __shared__ float stb[512];
    __shared__ float stsq[64];
    __shared__ float sq[64];
    __shared__ float sb[64];
    __shared__ float sie[8];
    int tid = threadIdx.x;
    int bid = blockIdx.x;
    int gen = 0;
    const float al = g_alpha[0];
    const float om = 1.f - al;

    if (tid < 64){
        sq[tid] = g_q[tid];
        int p = tid >> 3, k2 = tid & 7;
        stsq[p*8 + k2] = g_tsqq[k2*8 + p];
    }

    const int B0 = bid * NPB;
    const int B1 = (B0 + NPB < NN) ? (B0 + NPB) : NN;
    const int k = tid & 7;
    const int nofs = tid >> 3;     // 0..127

    for (int t = 0; t < 5; t++){
        // ---- spmm phase (t>0): block-own rows, no barrier before cost ----
        if (t > 0) spmm_phase(B0, B1, tid);
        // ---- cost phase ----
        if (t == 0){
            if (tid < 64){ int p = tid >> 3, k2 = tid & 7; stb[p*8+k2] = g_tq2[k2*8+p]; }
        } else {
            if (tid < 512){
                int p = tid >> 6, m = (tid >> 3) & 7, k2 = tid & 7;
                stb[tid] = 2.f * sb[k2*8+m] * tmpl[k2*64 + p*8 + m];
            }
        }
        __syncthreads();
        float cabs = 0.f;
        for (int n = B0 + nofs; n < B1; n += 128){
            float d = (float)g_deg[n] * INV_N;
            const float4* mp = (const float4*)&g_Mfeat[(size_t)n*KM + k*8];
            float4 m0 = mp[0], m1 = mp[1];
            float mf[8] = {m0.x,m0.y,m0.z,m0.w,m1.x,m1.y,m1.z,m1.w};
            float cc[8];
            if (t == 0){
                #pragma unroll
                for (int p = 0; p < 8; p++)
                    cc[p] = d + stsq[p*8+k] - d*stb[p*8+k];
            } else {
                const float4* cp0 = (const float4*)&g_CT[(size_t)n*KM + k*8];
                float4 t0 = cp0[0], t1 = cp0[1];
                float ct[8] = {t0.x,t0.y,t0.z,t0.w,t1.x,t1.y,t1.z,t1.w};
                #pragma unroll
                for (int p = 0; p < 8; p++){
                    float s = 0.f;
                    #pragma unroll
                    for (int m = 0; m < 8; m++)
                        s = fmaf(ct[m], stb[p*64 + m*8 + k], s);
                    cc[p] = d + stsq[p*8+k] - s;
                }
            }
            #pragma unroll
            for (int p = 0; p < 8; p++){
                cc[p] = al*cc[p] + om*mf[p];
                cabs += fabsf(cc[p]);
            }
            float4 o0 = make_float4(cc[0],cc[1],cc[2],cc[3]);
            float4 o1 = make_float4(cc[4],cc[5],cc[6],cc[7]);
            float4* cp = (float4*)&g_CT[(size_t)n*KM + k*8];
            cp[0] = o0; cp[1] = o1;
        }
        {
            unsigned full = 0xffffffffu;
            cabs += __shfl_down_sync(full, cabs, 16);
            cabs += __shfl_down_sync(full, cabs, 8);
            int lane = tid & 31, wp = tid >> 5;
            if (lane < 8) buf[wp*8 + lane] = cabs;
            __syncthreads();
            if (tid < 8){
                float s = 0.f;
                #pragma unroll
                for (int w = 0; w < 32; w++) s += buf[w*8 + tid];
                __stcg(&g_Pabs[bid*8 + tid], s);
            }
        }
        gridbar(gen);
        // ---- eps + exp init phase ----
        if (tid < 256){
            int kk = tid & 7, r = tid >> 3;
            float s = 0.f;
            for (int i = r; i < NB; i += 32) s += __ldcg(&g_Pabs[i*8 + kk]);
            buf[tid] = s;
        }
        __syncthreads();
        if (tid < 8){
            float s = 0.f;
            #pragma unroll
            for (int r = 0; r < 32; r++) s += buf[r*8 + tid];
            sie[tid] = (float)(NN*MM) / (EPSREL * s);
        }
        __syncthreads();
        const float ie = sie[k];
        float c[8];
        #pragma unroll
        for (int j = 0; j < 8; j++) c[j] = 0.f;
        for (int n = B0 + nofs; n < B1; n += 128){
            const float4* cp = (const float4*)&g_CT[(size_t)n*KM + k*8];
            float4 c0 = cp[0], c1 = cp[1];
            float u0 = __expf(-c0.x*ie), u1 = __expf(-c0.y*ie);
            float u2 = __expf(-c0.z*ie), u3 = __expf(-c0.w*ie);
            float u4 = __expf(-c1.x*ie), u5 = __expf(-c1.y*ie);
            float u6 = __expf(-c1.z*ie), u7 = __expf(-c1.w*ie);
            __nv_bfloat162 p0 = __floats2bfloat162_rn(u0,u1);
            __nv_bfloat162 p1 = __floats2bfloat162_rn(u2,u3);
            __nv_bfloat162 p2 = __floats2bfloat162_rn(u4,u5);
            __nv_bfloat162 p3 = __floats2bfloat162_rn(u6,u7);
            uint4 raw;
            raw.x = *(unsigned*)&p0; raw.y = *(unsigned*)&p1;
            raw.z = *(unsigned*)&p2; raw.w = *(unsigned*)&p3;
            *(uint4*)&g_Ub[(size_t)n*KM + k*8] = raw;
            float2 v0 = __bfloat1622float2(p0);
            float2 v1 = __bfloat1622float2(p1);
            float2 v2 = __bfloat1622float2(p2);
            float2 v3 = __bfloat1622float2(p3);
            c[0]+=v0.x; c[1]+=v0.y; c[2]+=v1.x; c[3]+=v1.y;
            c[4]+=v2.x; c[5]+=v2.y; c[6]+=v3.x; c[7]+=v3.y;
        }
        colreduce(c, buf, tid, &g_P0[bid*64]);
        gridbar(gen);
        // ---- 20 Sinkhorn iterations (U via L1-cached plain loads) ----
        for (int it = 0; it < 20; it++){
            const float* Pp = (it & 1) ? g_P1 : g_P0;
            float* Pn = (it & 1) ? g_P0 : g_P1;
            if (tid < 512){
                int km = tid & 63, r = tid >> 6;
                float s = 0.f;
                #pragma unroll 4
                for (int i = r; i < NB; i += 8) s += __ldcg(&Pp[i*64 + km]);
                buf[tid] = s;
            }
            __syncthreads();
            if (tid < 64){
                float s = 0.f;
                #pragma unroll
                for (int r = 0; r < 8; r++) s += buf[r*64 + tid];
                sb[tid] = __fdividef(sq[tid], s);
            }
            __syncthreads();
            float b0 = sb[k*8+0], b1 = sb[k*8+1], b2 = sb[k*8+2], b3 = sb[k*8+3];
            float b4 = sb[k*8+4], b5 = sb[k*8+5], b6 = sb[k*8+6], b7 = sb[k*8+7];
            if (it < 19){
                #pragma unroll
                for (int j = 0; j < 8; j++) c[j] = 0.f;
                for (int n = B0 + nofs; n < B1; n += 128){
                    uint4 raw = *(const uint4*)&g_Ub[(size_t)n*KM + k*8];
                    float2 u0 = __bfloat1622float2(*(__nv_bfloat162*)&raw.x);
                    float2 u1 = __bfloat1622float2(*(__nv_bfloat162*)&raw.y);
                    float2 u2 = __bfloat1622float2(*(__nv_bfloat162*)&raw.z);
                    float2 u3 = __bfloat1622float2(*(__nv_bfloat162*)&raw.w);
                    float s = b0*u0.x; s = fmaf(b1,u0.y,s);
                    s = fmaf(b2,u1.x,s); s = fmaf(b3,u1.y,s);
                    s = fmaf(b4,u2.x,s); s = fmaf(b5,u2.y,s);
                    s = fmaf(b6,u3.x,s); s = fmaf(b7,u3.y,s);
                    float a = __fdividef(INV_N, s);
                    c[0]=fmaf(a,u0.x,c[0]); c[1]=fmaf(a,u0.y,c[1]);
                    c[2]=fmaf(a,u1.x,c[2]); c[3]=fmaf(a,u1.y,c[3]);
                    c[4]=fmaf(a,u2.x,c[4]); c[5]=fmaf(a,u2.y,c[5]);
                    c[6]=fmaf(a,u3.x,c[6]); c[7]=fmaf(a,u3.y,c[7]);
                }
                colreduce(c, buf, tid, &Pn[bid*64]);
                gridbar(gen);
            } else {
                // final iteration: write AU = a*u (bf16), block-own
                for (int n = B0 + nofs; n < B1; n += 128){
                    uint4 raw = *(const uint4*)&g_Ub[(size_t)n*KM + k*8];
                    float2 u0 = __bfloat1622float2(*(__nv_bfloat162*)&raw.x);
                    float2 u1 = __bfloat1622float2(*(__nv_bfloat162*)&raw.y);
                    float2 u2 = __bfloat1622float2(*(__nv_bfloat162*)&raw.z);
                    float2 u3 = __bfloat1622float2(*(__nv_bfloat162*)&raw.w);
                    float s = b0*u0.x; s = fmaf(b1,u0.y,s);
                    s = fmaf(b2,u1.x,s); s = fmaf(b3,u1.y,s);
                    s = fmaf(b4,u2.x,s); s = fmaf(b5,u2.y,s);
                    s = fmaf(b6,u3.x,s); s = fmaf(b7,u3.y,s);
                    float a = __fdividef(INV_N, s);
                    __nv_bfloat162 q0 = __floats2bfloat162_rn(a*u0.x, a*u0.y);
                    __nv_bfloat162 q1 = __floats2bfloat162_rn(a*u1.x, a*u1.y);
                    __nv_bfloat162 q2 = __floats2bfloat162_rn(a*u2.x, a*u2.y);
                    __nv_bfloat162 q3 = __floats2bfloat162_rn(a*u3.x, a*u3.y);
                    uint4 aw;
                    aw.x = *(unsigned*)&q0; aw.y = *(unsigned*)&q1;
                    aw.z = *(unsigned*)&q2; aw.w = *(unsigned*)&q3;
                    *(uint4*)&g_AU[(size_t)n*KM + k*8] = aw;
                }
            }
        }
        gridbar(gen);   // AU visible for next spmm (cross-block gather)
    }
    // ---- final spmm with converged AU (block-own rows, no barrier) ----
    spmm_phase(B0, B1, tid);
    // ---- fgw partials ----
    if (tid < 512){
        int p = tid >> 6, m = (tid >> 3) & 7, k2 = tid & 7;
        stb[tid] = 2.f * sb[k2*8+m] * tmpl[k2*64 + p*8 + m];
    }
    __syncthreads();
    {
        double s1 = 0.0, s2 = 0.0;
        for (int n = B0 + nofs; n < B1; n += 128){
            float d = (float)g_deg[n] * INV_N;
            uint4 raw = *(const uint4*)&g_AU[(size_t)n*KM + k*8];
            float2 v0 = __bfloat1622float2(*(__nv_bfloat162*)&raw.x);
            float2 v1 = __bfloat1622float2(*(__nv_bfloat162*)&raw.y);
            float2 v2 = __bfloat1622float2(*(__nv_bfloat162*)&raw.z);
            float2 v3 = __bfloat1622float2(*(__nv_bfloat162*)&raw.w);
            float au[8] = {v0.x,v0.y,v1.x,v1.y,v2.x,v2.y,v3.x,v3.y};
            const float4* mp = (const float4*)&g_Mfeat[(size_t)n*KM + k*8];
            float4 m0 = mp[0], m1 = mp[1];
            float mf[8] = {m0.x,m0.y,m0.z,m0.w,m1.x,m1.y,m1.z,m1.w};
            const float4* cp0 = (const float4*)&g_CT[(size_t)n*KM + k*8];
            float4 t0 = cp0[0], t1 = cp0[1];
            float ct[8] = {t0.x,t0.y,t0.z,t0.w,t1.x,t1.y,t1.z,t1.w};
            float accM = 0.f, accT = 0.f;
            #pragma unroll
            for (int p = 0; p < 8; p++){
                float T = au[p] * sb[k*8+p];
                float s = 0.f;
                #pragma unroll
                for (int m = 0; m < 8; m++)
                    s = fmaf(ct[m], stb[p*64 + m*8 + k], s);
                float tens = d + stsq[p*8+k] - s;
                accM = fmaf(mf[p], T, accM);
                accT = fmaf(tens,  T, accT);
            }
            s1 += (double)accM;
            s2 += (double)accT;
        }
        unsigned full = 0xffffffffu;
        s1 += __shfl_down_sync(full, s1, 16);
        s1 += __shfl_down_sync(full, s1, 8);
        s2 += __shfl_down_sync(full, s2, 16);
        s2 += __shfl_down_sync(full, s2, 8);
        double* dbuf = (double*)buf;
        int lane = tid & 31, wp = tid >> 5;
        if (lane < 8){
            dbuf[wp*8 + lane] = s1;
            dbuf[256 + wp*8 + lane] = s2;
        }
        __syncthreads();
        if (tid < 16){
            int which = tid >> 3, k2 = tid & 7;
            double s = 0.0;
            #pragma unroll
            for (int w = 0; w < 32; w++) s += dbuf[which*256 + w*8 + k2];
            g_Fpart[bid*16 + which*8 + k2] = s;
        }
    }
    gridbar(gen);
    // ---- final output (block 0) ----
    if (bid == 0 && tid < 8){
        double sA = 0.0, sB = 0.0;
        for (int i = 0; i < NB; i++){
            sA += __ldcg(&g_Fpart[i*16 + tid]);
            sB += __ldcg(&g_Fpart[i*16 + 8 + tid]);
        }
        double ald = (double)al;
        out[tid] = (float)((1.0 - ald)*sA + ald*sB);
    }
}

// ------------------ launch ------------------
extern "C" void kernel_launch(void* const* d_in, const int* in_sizes, int n_in,
                              void* d_out, int out_size){
    const float* x    = (const float*)d_in[0];
    const int*   ei   = (const int*)  d_in[1];
    const float* tmpl = (const float*)d_in[2];
    const float* tf   = (const float*)d_in[3];
    const float* q0   = (const float*)d_in[4];
    const float* a0   = (const float*)d_in[5];
    float* out = (float*)d_out;
    const int* src = ei;
    const int* dst = ei + NE;

    k_small<<<1, 64>>>(q0, tmpl, tf, a0);
    k_zero<<<NZB, 1024>>>();
    k_hist<<<NEB, 1024>>>(src);
    k_scan1<<<NSC, 1024>>>();
    k_scan2<<<1, 128>>>();
    k_scan3<<<NSC, 1024>>>();
    k_fill<<<NEB, 1024>>>(src, dst);
    k_mfeat<<<NMF, 128>>>(x, tf);
    k_main<<<NB, 1024>>>(tmpl, out);
}

// round 15
// speedup vs baseline: 1.1038x; 1.0853x over previous
#include <cuda_runtime.h>
#include <cuda_bf16.h>
#include <math.h>

#define NN 100000
#define NE 1600000
#define FF 128
#define KK 8
#define MM 8
#define KM 64
#define EPSREL 0.05f
#define INV_N 1e-5f

#define NB 148                 /* persistent grid blocks */
#define NPB 676                /* nodes per block */
#define NEB ((NE + 1023)/1024) /* 1563 */
#define NMF ((NN + 127)/128)   /* 782 */
#define NZB ((NN + 1023)/1024) /* 98  */
#define NSPX ((NN + 7)/8)
#define NSC 98

// ------------------ static scratch (no allocations) ------------------
__device__ __align__(128) float g_Mfeat[(size_t)NN*KM];
__device__ __align__(128) __nv_bfloat16 g_Ub[(size_t)NN*KM];  // u (bf16)
__device__ __align__(128) __nv_bfloat16 g_AU[(size_t)NN*KM];  // a*u (bf16)
__device__ __align__(128) float g_CT[(size_t)NN*KM];          // spmm out / cost (fp32)
__device__ __align__(128) float g_xsq[NN];
__device__ __align__(128) float g_P0[NB*KM];
__device__ __align__(128) float g_P1[NB*KM];
__device__ __align__(128) float g_Pabs[NB*KK];
__device__ __align__(128) double g_Fpart[NB*16];
__device__ __align__(128) int   g_deg[NN];
__device__ __align__(128) int   g_rowptr[NN+1];
__device__ __align__(128) int   g_cursor[NN];
__device__ __align__(128) int   g_csrdst[NE];
__device__ __align__(128) int   g_bsum[NSC];
__device__ __align__(128) int   g_boff[NSC];
__device__ float g_q[KM];
__device__ float g_tsqq[KM];
__device__ float g_tq2[KM];
__device__ float g_tfsq[KM];
__device__ float g_alpha[1];
__device__ unsigned g_cnt;

// ---- lightweight release/acquire grid barrier (single counter, R6-proven) ----
__device__ __forceinline__ void gridbar(int &gen){
    __syncthreads();
    if (threadIdx.x == 0){
        unsigned tgt = (unsigned)(gen + 1) * (unsigned)NB;
        asm volatile("red.release.gpu.global.add.u32 [%0], %1;"
                     :: "l"(&g_cnt), "r"(1u) : "memory");
        unsigned v;
        do {
            asm volatile("ld.acquire.gpu.global.u32 %0, [%1];"
                         : "=r"(v) : "l"(&g_cnt) : "memory");
        } while (v < tgt);
    }
    gen++;
    __syncthreads();
}

// ------------------ small precompute (+ counter reset) ------------------
__global__ void k_small(const float* __restrict__ q0, const float* __restrict__ tmpl,
                        const float* __restrict__ tf, const float* __restrict__ a0){
    __shared__ float sq[KM];
    int t = threadIdx.x;  // 64 threads
    if (t == 0) g_cnt = 0u;
    if (t < KM){
        float s = 0.f;
        #pragma unroll 8
        for (int f = 0; f < FF; f++){ float v = tf[t*FF+f]; s = fmaf(v, v, s); }
        g_tfsq[t] = s;
    }
    if (t == 0) g_alpha[0] = 1.f/(1.f + expf(-a0[0]));
    if (t < KK){
        int k = t;
        float mx = -1e30f;
        for (int j = 0; j < MM; j++) mx = fmaxf(mx, q0[k*MM+j]);
        float e[MM]; float s = 0.f;
        for (int j = 0; j < MM; j++){ e[j] = expf(q0[k*MM+j]-mx); s += e[j]; }
        for (int j = 0; j < MM; j++) sq[k*MM+j] = e[j]/s;
    }
    __syncthreads();
    if (t < KM){
        int k = t >> 3, i = t & 7;
        float s = 0.f, s2 = 0.f;
        #pragma unroll
        for (int j = 0; j < MM; j++){
            float tv = tmpl[k*64 + i*8 + j];
            float qv = sq[k*8 + j];
            s  = fmaf(tv*tv, qv, s);
            s2 = fmaf(tv,    qv, s2);
        }
        g_tsqq[t] = s;
        g_tq2[t]  = 2.f*s2;
        g_q[t]    = sq[t];
    }
}

// ------------------ CSR build ------------------
__global__ void k_zero(){
    int i = blockIdx.x*1024 + threadIdx.x;
    if (i < NN) g_deg[i] = 0;
}
__global__ void k_hist(const int* __restrict__ src){
    int e = blockIdx.x*1024 + threadIdx.x;
    if (e < NE) atomicAdd(&g_deg[src[e]], 1);
}
__global__ __launch_bounds__(1024) void k_scan1(){
    __shared__ int ss[1024];
    int t = threadIdx.x;
    int idx = blockIdx.x*1024 + t;
    int v = (idx < NN) ? g_deg[idx] : 0;
    ss[t] = v;
    __syncthreads();
    #pragma unroll
    for (int off = 1; off < 1024; off <<= 1){
        int x = (t >= off) ? ss[t-off] : 0;
        __syncthreads();
        ss[t] += x;
        __syncthreads();
    }
    if (idx < NN) g_rowptr[idx] = ss[t] - v;
    if (t == 1023) g_bsum[blockIdx.x] = ss[t];
}
__global__ void k_scan2(){
    __shared__ int ss[128];
    int t = threadIdx.x;
    int v = (t < NSC) ? g_bsum[t] : 0;
    ss[t] = v;
    __syncthreads();
    #pragma unroll
    for (int off = 1; off < 128; off <<= 1){
        int x = (t >= off) ? ss[t-off] : 0;
        __syncthreads();
        ss[t] += x;
        __syncthreads();
    }
    if (t < NSC) g_boff[t] = ss[t] - v;
    if (t == 0) g_rowptr[NN] = NE;
}
__global__ void k_scan3(){
    int idx = blockIdx.x*1024 + threadIdx.x;
    if (idx < NN){
        int r = g_rowptr[idx] + g_boff[blockIdx.x];
        g_rowptr[idx] = r;
        g_cursor[idx] = r;
    }
}
__global__ void k_fill(const int* __restrict__ src, const int* __restrict__ dst){
    int e = blockIdx.x*1024 + threadIdx.x;
    if (e < NE){
        int s = src[e];
        int pos = atomicAdd(&g_cursor[s], 1);
        g_csrdst[pos] = dst[e];
    }
}

// ------------------ |x|^2 per node ------------------
__global__ __launch_bounds__(256) void k_xsq(const float* __restrict__ x){
    int w = (blockIdx.x*256 + threadIdx.x) >> 5;
    int lane = threadIdx.x & 31;
    if (w >= NN) return;
    float4 v = *(const float4*)&x[(size_t)w*FF + lane*4];
    float s = v.x*v.x + v.y*v.y + v.z*v.z + v.w*v.w;
    #pragma unroll
    for (int o = 16; o > 0; o >>= 1) s += __shfl_down_sync(0xffffffffu, s, o);
    if (lane == 0) g_xsq[w] = s;
}

// ------------------ Mfeat GEMM: 128-node x 64-col tile, 8x8 per thread ------------------
__global__ __launch_bounds__(128) void k_mfeat(const float* __restrict__ x,
                                               const float* __restrict__ tf){
    __shared__ float xs[16][132];
    __shared__ float ts[16][68];
    int tid = threadIdx.x;
    int n0 = blockIdx.x * 128;
    int ty = tid >> 3, tx = tid & 7;
    float acc[8][8];
    #pragma unroll
    for (int i = 0; i < 8; i++)
        #pragma unroll
        for (int j = 0; j < 8; j++) acc[i][j] = 0.f;
    int q = tid & 3, r0 = tid >> 2;
    int rt = tid >> 1, qt = (tid & 1) * 8;
    for (int kb = 0; kb < FF; kb += 16){
        #pragma unroll
        for (int itr = 0; itr < 4; itr++){
            int r = r0 + itr*32;
            int n = n0 + r;
            float4 v = make_float4(0.f,0.f,0.f,0.f);
            if (n < NN) v = *(const float4*)&x[(size_t)n*FF + kb + q*4];
            xs[q*4+0][r] = v.x; xs[q*4+1][r] = v.y;
            xs[q*4+2][r] = v.z; xs[q*4+3][r] = v.w;
        }
        {
            float4 a = *(const float4*)&tf[(size_t)rt*FF + kb + qt];
            float4 b = *(const float4*)&tf[(size_t)rt*FF + kb + qt + 4];
            ts[qt+0][rt] = a.x; ts[qt+1][rt] = a.y; ts[qt+2][rt] = a.z; ts[qt+3][rt] = a.w;
            ts[qt+4][rt] = b.x; ts[qt+5][rt] = b.y; ts[qt+6][rt] = b.z; ts[qt+7][rt] = b.w;
        }
        __syncthreads();
        #pragma unroll
        for (int kk = 0; kk < 16; kk++){
            float4 A0 = *(const float4*)&xs[kk][ty*8];
            float4 A1 = *(const float4*)&xs[kk][ty*8+4];
            float4 B0 = *(const float4*)&ts[kk][tx*8];
            float4 B1 = *(const float4*)&ts[kk][tx*8+4];
            float av[8] = {A0.x,A0.y,A0.z,A0.w,A1.x,A1.y,A1.z,A1.w};
            float bv[8] = {B0.x,B0.y,B0.z,B0.w,B1.x,B1.y,B1.z,B1.w};
            #pragma unroll
            for (int i = 0; i < 8; i++)
                #pragma unroll
                for (int j = 0; j < 8; j++)
                    acc[i][j] = fmaf(av[i], bv[j], acc[i][j]);
        }
        __syncthreads();
    }
    #pragma unroll
    for (int i = 0; i < 8; i++){
        int n = n0 + ty*8 + i;
        if (n < NN){
            float xq = g_xsq[n];
            int c = tx*8;
            float4 o0, o1;
            o0.x = xq + g_tfsq[c+0] - 2.f*acc[i][0];
            o0.y = xq + g_tfsq[c+1] - 2.f*acc[i][1];
            o0.z = xq + g_tfsq[c+2] - 2.f*acc[i][2];
            o0.w = xq + g_tfsq[c+3] - 2.f*acc[i][3];
            o1.x = xq + g_tfsq[c+4] - 2.f*acc[i][4];
            o1.y = xq + g_tfsq[c+5] - 2.f*acc[i][5];
            o1.z = xq + g_tfsq[c+6] - 2.f*acc[i][6];
            o1.w = xq + g_tfsq[c+7] - 2.f*acc[i][7];
            *(float4*)&g_Mfeat[(size_t)n*KM + c]     = o0;
            *(float4*)&g_Mfeat[(size_t)n*KM + c + 4] = o1;
        }
    }
}

// ------------------ column-sum partial reduce helper ------------------
__device__ __forceinline__ void colreduce(float* c, float* buf, int tid, float* dst){
    unsigned full = 0xffffffffu;
    #pragma unroll
    for (int j = 0; j < 8; j++){
        c[j] += __shfl_down_sync(full, c[j], 16);
        c[j] += __shfl_down_sync(full, c[j], 8);
    }
    int lane = tid & 31, wp = tid >> 5;
    if (lane < 8){
        #pragma unroll
        for (int j = 0; j < 8; j++) buf[j*256 + wp*8 + lane] = c[j];
    }
    __syncthreads();
    if (tid < 64){
        int j = tid >> 3, kk = tid & 7;
        float s = 0.f;
        #pragma unroll
        for (int w = 0; w < 32; w++) s += buf[j*256 + w*8 + kk];
        __stcg(&dst[kk*8 + j], s);
    }
}

// ---- spmm: CTraw[r][c] = sum_{d in row r} AU[d][c], BLOCK-OWN rows ----
__device__ __forceinline__ void spmm_phase(int B0, int B1, int tid){
    int lane = tid & 31;
    int c2 = lane*2;
    for (int r = B0 + (tid >> 5); r < B1; r += 32){
        int beg = g_rowptr[r], end = g_rowptr[r+1];
        float ax = 0.f, ay = 0.f;
        #pragma unroll 4
        for (int e = beg; e < end; e++){
            int d = g_csrdst[e];
            unsigned uraw = __ldcg((const unsigned*)&g_AU[(size_t)d*KM + c2]);
            float2 u = __bfloat1622float2(*(__nv_bfloat162*)&uraw);
            ax += u.x;
            ay += u.y;
        }
        float2 o = make_float2(ax, ay);
        *(float2*)&g_CT[(size_t)r*KM + c2] = o;
    }
}

// ------------------ the big persistent kernel ------------------
__global__ __launch_bounds__(1024, 1) void k_main(const float* __restrict__ tmpl,
                                                  float* __restrict__ out){
    __shared__ __align__(16) float buf[2048];
    __shared__ float stb[512];
    __shared__ float stsq[64];
    __shared__ float sq[64];
    __shared__ float sb[64];
    __shared__ float sie[8];
    int tid = threadIdx.x;
    int bid = blockIdx.x;
    int gen = 0;
    const float al = g_alpha[0];
    const float om = 1.f - al;

    if (tid < 64){
        sq[tid] = g_q[tid];
        int p = tid >> 3, k2 = tid & 7;
        stsq[p*8 + k2] = g_tsqq[k2*8 + p];
    }

    const int B0 = bid * NPB;
    const int B1 = (B0 + NPB < NN) ? (B0 + NPB) : NN;
    const int k = tid & 7;
    const int nofs = tid >> 3;     // 0..127

    for (int t = 0; t < 5; t++){
        // ---- spmm phase (t>0): block-own rows, no barrier before cost ----
        if (t > 0) spmm_phase(B0, B1, tid);
        // ---- cost phase ----
        if (t == 0){
            if (tid < 64){ int p = tid >> 3, k2 = tid & 7; stb[p*8+k2] = g_tq2[k2*8+p]; }
        } else {
            if (tid < 512){
                int p = tid >> 6, m = (tid >> 3) & 7, k2 = tid & 7;
                stb[tid] = 2.f * sb[k2*8+m] * tmpl[k2*64 + p*8 + m];
            }
        }
        __syncthreads();
        float cabs = 0.f;
        for (int n = B0 + nofs; n < B1; n += 128){
            float d = (float)g_deg[n] * INV_N;
            const float4* mp = (const float4*)&g_Mfeat[(size_t)n*KM + k*8];
            float4 m0 = mp[0], m1 = mp[1];
            float mf[8] = {m0.x,m0.y,m0.z,m0.w,m1.x,m1.y,m1.z,m1.w};
            float cc[8];
            if (t == 0){
                #pragma unroll
                for (int p = 0; p < 8; p++)
                    cc[p] = d + stsq[p*8+k] - d*stb[p*8+k];
            } else {
                const float4* cp0 = (const float4*)&g_CT[(size_t)n*KM + k*8];
                float4 t0 = cp0[0], t1 = cp0[1];
                float ct[8] = {t0.x,t0.y,t0.z,t0.w,t1.x,t1.y,t1.z,t1.w};
                #pragma unroll
                for (int p = 0; p < 8; p++){
                    float s = 0.f;
                    #pragma unroll
                    for (int m = 0; m < 8; m++)
                        s = fmaf(ct[m], stb[p*64 + m*8 + k], s);
                    cc[p] = d + stsq[p*8+k] - s;
                }
            }
            #pragma unroll
            for (int p = 0; p < 8; p++){
                cc[p] = al*cc[p] + om*mf[p];
                cabs += fabsf(cc[p]);
            }
            float4 o0 = make_float4(cc[0],cc[1],cc[2],cc[3]);
            float4 o1 = make_float4(cc[4],cc[5],cc[6],cc[7]);
            float4* cp = (float4*)&g_CT[(size_t)n*KM + k*8];
            cp[0] = o0; cp[1] = o1;
        }
        {
            unsigned full = 0xffffffffu;
            cabs += __shfl_down_sync(full, cabs, 16);
            cabs += __shfl_down_sync(full, cabs, 8);
            int lane = tid & 31, wp = tid >> 5;
            if (lane < 8) buf[wp*8 + lane] = cabs;
            __syncthreads();
            if (tid < 8){
                float s = 0.f;
                #pragma unroll
                for (int w = 0; w < 32; w++) s += buf[w*8 + tid];
                __stcg(&g_Pabs[bid*8 + tid], s);
            }
        }
        gridbar(gen);
        // ---- eps + exp init phase ----
        if (tid < 256){
            int kk = tid & 7, r = tid >> 3;
            float s = 0.f;
            for (int i = r; i < NB; i += 32) s += __ldcg(&g_Pabs[i*8 + kk]);
            buf[tid] = s;
        }
        __syncthreads();
        if (tid < 8){
            float s = 0.f;
            #pragma unroll
            for (int r = 0; r < 32; r++) s += buf[r*8 + tid];
            sie[tid] = (float)(NN*MM) / (EPSREL * s);
        }
        __syncthreads();
        const float ie = sie[k];
        float c[8];
        #pragma unroll
        for (int j = 0; j < 8; j++) c[j] = 0.f;
        for (int n = B0 + nofs; n < B1; n += 128){
            const float4* cp = (const float4*)&g_CT[(size_t)n*KM + k*8];
            float4 c0 = cp[0], c1 = cp[1];
            float u0 = __expf(-c0.x*ie), u1 = __expf(-c0.y*ie);
            float u2 = __expf(-c0.z*ie), u3 = __expf(-c0.w*ie);
            float u4 = __expf(-c1.x*ie), u5 = __expf(-c1.y*ie);
            float u6 = __expf(-c1.z*ie), u7 = __expf(-c1.w*ie);
            __nv_bfloat162 p0 = __floats2bfloat162_rn(u0,u1);
            __nv_bfloat162 p1 = __floats2bfloat162_rn(u2,u3);
            __nv_bfloat162 p2 = __floats2bfloat162_rn(u4,u5);
            __nv_bfloat162 p3 = __floats2bfloat162_rn(u6,u7);
            uint4 raw;
            raw.x = *(unsigned*)&p0; raw.y = *(unsigned*)&p1;
            raw.z = *(unsigned*)&p2; raw.w = *(unsigned*)&p3;
            *(uint4*)&g_Ub[(size_t)n*KM + k*8] = raw;
            float2 v0 = __bfloat1622float2(p0);
            float2 v1 = __bfloat1622float2(p1);
            float2 v2 = __bfloat1622float2(p2);
            float2 v3 = __bfloat1622float2(p3);
            c[0]+=v0.x; c[1]+=v0.y; c[2]+=v1.x; c[3]+=v1.y;
            c[4]+=v2.x; c[5]+=v2.y; c[6]+=v3.x; c[7]+=v3.y;
        }
        colreduce(c, buf, tid, &g_P0[bid*64]);
        gridbar(gen);
        // ---- 20 Sinkhorn iterations (U via L1-cached plain loads) ----
        for (int it = 0; it < 20; it++){
            const float* Pp = (it & 1) ? g_P1 : g_P0;
            float* Pn = (it & 1) ? g_P0 : g_P1;
            {   // 1024-thread b-partial reduce (16 rows x 64 km)
                int km = tid & 63, r = tid >> 6;
                float s = 0.f;
                #pragma unroll 4
                for (int i = r; i < NB; i += 16) s += __ldcg(&Pp[i*64 + km]);
                buf[tid] = s;
            }
            __syncthreads();
            if (tid < 64){
                float s = 0.f;
                #pragma unroll
                for (int r = 0; r < 16; r++) s += buf[r*64 + tid];
                sb[tid] = __fdividef(sq[tid], s);
            }
            __syncthreads();
            float b0 = sb[k*8+0], b1 = sb[k*8+1], b2 = sb[k*8+2], b3 = sb[k*8+3];
            float b4 = sb[k*8+4], b5 = sb[k*8+5], b6 = sb[k*8+6], b7 = sb[k*8+7];
            if (it < 19){
                #pragma unroll
                for (int j = 0; j < 8; j++) c[j] = 0.f;
                for (int n = B0 + nofs; n < B1; n += 128){
                    uint4 raw = *(const uint4*)&g_Ub[(size_t)n*KM + k*8];
                    float2 u0 = __bfloat1622float2(*(__nv_bfloat162*)&raw.x);
                    float2 u1 = __bfloat1622float2(*(__nv_bfloat162*)&raw.y);
                    float2 u2 = __bfloat1622float2(*(__nv_bfloat162*)&raw.z);
                    float2 u3 = __bfloat1622float2(*(__nv_bfloat162*)&raw.w);
                    float s = b0*u0.x; s = fmaf(b1,u0.y,s);
                    s = fmaf(b2,u1.x,s); s = fmaf(b3,u1.y,s);
                    s = fmaf(b4,u2.x,s); s = fmaf(b5,u2.y,s);
                    s = fmaf(b6,u3.x,s); s = fmaf(b7,u3.y,s);
                    float a = __fdividef(INV_N, s);
                    c[0]=fmaf(a,u0.x,c[0]); c[1]=fmaf(a,u0.y,c[1]);
                    c[2]=fmaf(a,u1.x,c[2]); c[3]=fmaf(a,u1.y,c[3]);
                    c[4]=fmaf(a,u2.x,c[4]); c[5]=fmaf(a,u2.y,c[5]);
                    c[6]=fmaf(a,u3.x,c[6]); c[7]=fmaf(a,u3.y,c[7]);
                }
                colreduce(c, buf, tid, &Pn[bid*64]);
                gridbar(gen);
            } else {
                // final iteration: write AU = a*u (bf16), block-own
                for (int n = B0 + nofs; n < B1; n += 128){
                    uint4 raw = *(const uint4*)&g_Ub[(size_t)n*KM + k*8];
                    float2 u0 = __bfloat1622float2(*(__nv_bfloat162*)&raw.x);
                    float2 u1 = __bfloat1622float2(*(__nv_bfloat162*)&raw.y);
                    float2 u2 = __bfloat1622float2(*(__nv_bfloat162*)&raw.z);
                    float2 u3 = __bfloat1622float2(*(__nv_bfloat162*)&raw.w);
                    float s = b0*u0.x; s = fmaf(b1,u0.y,s);
                    s = fmaf(b2,u1.x,s); s = fmaf(b3,u1.y,s);
                    s = fmaf(b4,u2.x,s); s = fmaf(b5,u2.y,s);
                    s = fmaf(b6,u3.x,s); s = fmaf(b7,u3.y,s);
                    float a = __fdividef(INV_N, s);
                    __nv_bfloat162 q0 = __floats2bfloat162_rn(a*u0.x, a*u0.y);
                    __nv_bfloat162 q1 = __floats2bfloat162_rn(a*u1.x, a*u1.y);
                    __nv_bfloat162 q2 = __floats2bfloat162_rn(a*u2.x, a*u2.y);
                    __nv_bfloat162 q3 = __floats2bfloat162_rn(a*u3.x, a*u3.y);
                    uint4 aw;
                    aw.x = *(unsigned*)&q0; aw.y = *(unsigned*)&q1;
                    aw.z = *(unsigned*)&q2; aw.w = *(unsigned*)&q3;
                    *(uint4*)&g_AU[(size_t)n*KM + k*8] = aw;
                }
            }
        }
        gridbar(gen);   // AU visible for next spmm (cross-block gather)
    }
    // ---- final spmm with converged AU (block-own rows, no barrier) ----
    spmm_phase(B0, B1, tid);
    // ---- fgw partials ----
    if (tid < 512){
        int p = tid >> 6, m = (tid >> 3) & 7, k2 = tid & 7;
        stb[tid] = 2.f * sb[k2*8+m] * tmpl[k2*64 + p*8 + m];
    }
    __syncthreads();
    {
        double s1 = 0.0, s2 = 0.0;
        for (int n = B0 + nofs; n < B1; n += 128){
            float d = (float)g_deg[n] * INV_N;
            uint4 raw = *(const uint4*)&g_AU[(size_t)n*KM + k*8];
            float2 v0 = __bfloat1622float2(*(__nv_bfloat162*)&raw.x);
            float2 v1 = __bfloat1622float2(*(__nv_bfloat162*)&raw.y);
            float2 v2 = __bfloat1622float2(*(__nv_bfloat162*)&raw.z);
            float2 v3 = __bfloat1622float2(*(__nv_bfloat162*)&raw.w);
            float au[8] = {v0.x,v0.y,v1.x,v1.y,v2.x,v2.y,v3.x,v3.y};
            const float4* mp = (const float4*)&g_Mfeat[(size_t)n*KM + k*8];
            float4 m0 = mp[0], m1 = mp[1];
            float mf[8] = {m0.x,m0.y,m0.z,m0.w,m1.x,m1.y,m1.z,m1.w};
            const float4* cp0 = (const float4*)&g_CT[(size_t)n*KM + k*8];
            float4 t0 = cp0[0], t1 = cp0[1];
            float ct[8] = {t0.x,t0.y,t0.z,t0.w,t1.x,t1.y,t1.z,t1.w};
            float accM = 0.f, accT = 0.f;
            #pragma unroll
            for (int p = 0; p < 8; p++){
                float T = au[p] * sb[k*8+p];
                float s = 0.f;
                #pragma unroll
                for (int m = 0; m < 8; m++)
                    s = fmaf(ct[m], stb[p*64 + m*8 + k], s);
                float tens = d + stsq[p*8+k] - s;
                accM = fmaf(mf[p], T, accM);
                accT = fmaf(tens,  T, accT);
            }
            s1 += (double)accM;
            s2 += (double)accT;
        }
        unsigned full = 0xffffffffu;
        s1 += __shfl_down_sync(full, s1, 16);
        s1 += __shfl_down_sync(full, s1, 8);
        s2 += __shfl_down_sync(full, s2, 16);
        s2 += __shfl_down_sync(full, s2, 8);
        double* dbuf = (double*)buf;
        int lane = tid & 31, wp = tid >> 5;
        if (lane < 8){
            dbuf[wp*8 + lane] = s1;
            dbuf[256 + wp*8 + lane] = s2;
        }
        __syncthreads();
        if (tid < 16){
            int which = tid >> 3, k2 = tid & 7;
            double s = 0.0;
            #pragma unroll
            for (int w = 0; w < 32; w++) s += dbuf[which*256 + w*8 + k2];
            g_Fpart[bid*16 + which*8 + k2] = s;
        }
    }
    gridbar(gen);
    // ---- final output (block 0) ----
    if (bid == 0 && tid < 8){
        double sA = 0.0, sB = 0.0;
        for (int i = 0; i < NB; i++){
            sA += __ldcg(&g_Fpart[i*16 + tid]);
            sB += __ldcg(&g_Fpart[i*16 + 8 + tid]);
        }
        double ald = (double)al;
        out[tid] = (float)((1.0 - ald)*sA + ald*sB);
    }
}

// ------------------ launch ------------------
extern "C" void kernel_launch(void* const* d_in, const int* in_sizes, int n_in,
                              void* d_out, int out_size){
    const float* x    = (const float*)d_in[0];
    const int*   ei   = (const int*)  d_in[1];
    const float* tmpl = (const float*)d_in[2];
    const float* tf   = (const float*)d_in[3];
    const float* q0   = (const float*)d_in[4];
    const float* a0   = (const float*)d_in[5];
    float* out = (float*)d_out;
    const int* src = ei;
    const int* dst = ei + NE;

    k_small<<<1, 64>>>(q0, tmpl, tf, a0);
    k_zero<<<NZB, 1024>>>();
    k_hist<<<NEB, 1024>>>(src);
    k_scan1<<<NSC, 1024>>>();
    k_scan2<<<1, 128>>>();
    k_scan3<<<NSC, 1024>>>();
    k_fill<<<NEB, 1024>>>(src, dst);
    k_xsq<<<NSPX, 256>>>(x);
    k_mfeat<<<NMF, 128>>>(x, tf);
    k_main<<<NB, 1024>>>(tmpl, out);
}

// round 16
// speedup vs baseline: 1.1120x; 1.0074x over previous
#include <cuda_runtime.h>
#include <cuda_bf16.h>
#include <math.h>

#define NN 100000
#define NE 1600000
#define FF 128
#define KK 8
#define MM 8
#define KM 64
#define EPSREL 0.05f
#define INV_N 1e-5f

#define NB 148                 /* persistent grid blocks */
#define NPB 676                /* nodes per block */
#define NEB ((NE + 1023)/1024) /* 1563 */
#define NMF ((NN + 127)/128)   /* 782 */
#define NZB ((NN + 1023)/1024) /* 98  */
#define NSPX ((NN + 7)/8)
#define NSC 98

// ------------------ static scratch (no allocations) ------------------
__device__ __align__(128) float g_Mfeat[(size_t)NN*KM];
__device__ __align__(128) __nv_bfloat16 g_Ub[(size_t)NN*KM];  // u (bf16)
__device__ __align__(128) __nv_bfloat16 g_AU[(size_t)NN*KM];  // a*u (bf16)
__device__ __align__(128) float g_CT[(size_t)NN*KM];          // spmm out / cost (fp32)
__device__ __align__(128) float g_xsq[NN];
__device__ __align__(128) float g_P0[NB*KM];
__device__ __align__(128) float g_P1[NB*KM];
__device__ __align__(128) float g_Pabs[NB*KK];
__device__ __align__(128) double g_Fpart[NB*16];
__device__ __align__(128) int   g_deg[NN];
__device__ __align__(128) int   g_rowptr[NN+1];
__device__ __align__(128) int   g_cursor[NN];
__device__ __align__(128) int   g_csrdst[NE];
__device__ __align__(128) int   g_bsum[NSC];
__device__ __align__(128) int   g_boff[NSC];
__device__ float g_q[KM];
__device__ float g_tsqq[KM];
__device__ float g_tq2[KM];
__device__ float g_tfsq[KM];
__device__ float g_alpha[1];
__device__ unsigned g_cnt;

// ---- lightweight release/acquire grid barrier (single counter, R6-proven) ----
__device__ __forceinline__ void gridbar(int &gen){
    __syncthreads();
    if (threadIdx.x == 0){
        unsigned tgt = (unsigned)(gen + 1) * (unsigned)NB;
        asm volatile("red.release.gpu.global.add.u32 [%0], %1;"
                     :: "l"(&g_cnt), "r"(1u) : "memory");
        unsigned v;
        do {
            asm volatile("ld.acquire.gpu.global.u32 %0, [%1];"
                         : "=r"(v) : "l"(&g_cnt) : "memory");
        } while (v < tgt);
    }
    gen++;
    __syncthreads();
}

// ------------------ small precompute (+ counter reset) ------------------
__global__ void k_small(const float* __restrict__ q0, const float* __restrict__ tmpl,
                        const float* __restrict__ tf, const float* __restrict__ a0){
    __shared__ float sq[KM];
    int t = threadIdx.x;  // 64 threads
    if (t == 0) g_cnt = 0u;
    if (t < KM){
        float s = 0.f;
        #pragma unroll 8
        for (int f = 0; f < FF; f++){ float v = tf[t*FF+f]; s = fmaf(v, v, s); }
        g_tfsq[t] = s;
    }
    if (t == 0) g_alpha[0] = 1.f/(1.f + expf(-a0[0]));
    if (t < KK){
        int k = t;
        float mx = -1e30f;
        for (int j = 0; j < MM; j++) mx = fmaxf(mx, q0[k*MM+j]);
        float e[MM]; float s = 0.f;
        for (int j = 0; j < MM; j++){ e[j] = expf(q0[k*MM+j]-mx); s += e[j]; }
        for (int j = 0; j < MM; j++) sq[k*MM+j] = e[j]/s;
    }
    __syncthreads();
    if (t < KM){
        int k = t >> 3, i = t & 7;
        float s = 0.f, s2 = 0.f;
        #pragma unroll
        for (int j = 0; j < MM; j++){
            float tv = tmpl[k*64 + i*8 + j];
            float qv = sq[k*8 + j];
            s  = fmaf(tv*tv, qv, s);
            s2 = fmaf(tv,    qv, s2);
        }
        g_tsqq[t] = s;
        g_tq2[t]  = 2.f*s2;
        g_q[t]    = sq[t];
    }
}

// ------------------ CSR build ------------------
__global__ void k_zero(){
    int i = blockIdx.x*1024 + threadIdx.x;
    if (i < NN) g_deg[i] = 0;
}
__global__ void k_hist(const int* __restrict__ src){
    int e = blockIdx.x*1024 + threadIdx.x;
    if (e < NE) atomicAdd(&g_deg[src[e]], 1);
}
__global__ __launch_bounds__(1024) void k_scan1(){
    __shared__ int ss[1024];
    int t = threadIdx.x;
    int idx = blockIdx.x*1024 + t;
    int v = (idx < NN) ? g_deg[idx] : 0;
    ss[t] = v;
    __syncthreads();
    #pragma unroll
    for (int off = 1; off < 1024; off <<= 1){
        int x = (t >= off) ? ss[t-off] : 0;
        __syncthreads();
        ss[t] += x;
        __syncthreads();
    }
    if (idx < NN) g_rowptr[idx] = ss[t] - v;
    if (t == 1023) g_bsum[blockIdx.x] = ss[t];
}
__global__ void k_scan2(){
    __shared__ int ss[128];
    int t = threadIdx.x;
    int v = (t < NSC) ? g_bsum[t] : 0;
    ss[t] = v;
    __syncthreads();
    #pragma unroll
    for (int off = 1; off < 128; off <<= 1){
        int x = (t >= off) ? ss[t-off] : 0;
        __syncthreads();
        ss[t] += x;
        __syncthreads();
    }
    if (t < NSC) g_boff[t] = ss[t] - v;
    if (t == 0) g_rowptr[NN] = NE;
}
__global__ void k_scan3(){
    int idx = blockIdx.x*1024 + threadIdx.x;
    if (idx < NN){
        int r = g_rowptr[idx] + g_boff[blockIdx.x];
        g_rowptr[idx] = r;
        g_cursor[idx] = r;
    }
}
__global__ void k_fill(const int* __restrict__ src, const int* __restrict__ dst){
    int e = blockIdx.x*1024 + threadIdx.x;
    if (e < NE){
        int s = src[e];
        int pos = atomicAdd(&g_cursor[s], 1);
        g_csrdst[pos] = dst[e];
    }
}

// ------------------ |x|^2 per node ------------------
__global__ __launch_bounds__(256) void k_xsq(const float* __restrict__ x){
    int w = (blockIdx.x*256 + threadIdx.x) >> 5;
    int lane = threadIdx.x & 31;
    if (w >= NN) return;
    float4 v = *(const float4*)&x[(size_t)w*FF + lane*4];
    float s = v.x*v.x + v.y*v.y + v.z*v.z + v.w*v.w;
    #pragma unroll
    for (int o = 16; o > 0; o >>= 1) s += __shfl_down_sync(0xffffffffu, s, o);
    if (lane == 0) g_xsq[w] = s;
}

// ------------------ Mfeat GEMM: 128-node x 64-col tile, 8x8 per thread ------------------
__global__ __launch_bounds__(128) void k_mfeat(const float* __restrict__ x,
                                               const float* __restrict__ tf){
    __shared__ float xs[16][132];
    __shared__ float ts[16][68];
    int tid = threadIdx.x;
    int n0 = blockIdx.x * 128;
    int ty = tid >> 3, tx = tid & 7;
    float acc[8][8];
    #pragma unroll
    for (int i = 0; i < 8; i++)
        #pragma unroll
        for (int j = 0; j < 8; j++) acc[i][j] = 0.f;
    int q = tid & 3, r0 = tid >> 2;
    int rt = tid >> 1, qt = (tid & 1) * 8;
    for (int kb = 0; kb < FF; kb += 16){
        #pragma unroll
        for (int itr = 0; itr < 4; itr++){
            int r = r0 + itr*32;
            int n = n0 + r;
            float4 v = make_float4(0.f,0.f,0.f,0.f);
            if (n < NN) v = *(const float4*)&x[(size_t)n*FF + kb + q*4];
            xs[q*4+0][r] = v.x; xs[q*4+1][r] = v.y;
            xs[q*4+2][r] = v.z; xs[q*4+3][r] = v.w;
        }
        {
            float4 a = *(const float4*)&tf[(size_t)rt*FF + kb + qt];
            float4 b = *(const float4*)&tf[(size_t)rt*FF + kb + qt + 4];
            ts[qt+0][rt] = a.x; ts[qt+1][rt] = a.y; ts[qt+2][rt] = a.z; ts[qt+3][rt] = a.w;
            ts[qt+4][rt] = b.x; ts[qt+5][rt] = b.y; ts[qt+6][rt] = b.z; ts[qt+7][rt] = b.w;
        }
        __syncthreads();
        #pragma unroll
        for (int kk = 0; kk < 16; kk++){
            float4 A0 = *(const float4*)&xs[kk][ty*8];
            float4 A1 = *(const float4*)&xs[kk][ty*8+4];
            float4 B0 = *(const float4*)&ts[kk][tx*8];
            float4 B1 = *(const float4*)&ts[kk][tx*8+4];
            float av[8] = {A0.x,A0.y,A0.z,A0.w,A1.x,A1.y,A1.z,A1.w};
            float bv[8] = {B0.x,B0.y,B0.z,B0.w,B1.x,B1.y,B1.z,B1.w};
            #pragma unroll
            for (int i = 0; i < 8; i++)
                #pragma unroll
                for (int j = 0; j < 8; j++)
                    acc[i][j] = fmaf(av[i], bv[j], acc[i][j]);
        }
        __syncthreads();
    }
    #pragma unroll
    for (int i = 0; i < 8; i++){
        int n = n0 + ty*8 + i;
        if (n < NN){
            float xq = g_xsq[n];
            int c = tx*8;
            float4 o0, o1;
            o0.x = xq + g_tfsq[c+0] - 2.f*acc[i][0];
            o0.y = xq + g_tfsq[c+1] - 2.f*acc[i][1];
            o0.z = xq + g_tfsq[c+2] - 2.f*acc[i][2];
            o0.w = xq + g_tfsq[c+3] - 2.f*acc[i][3];
            o1.x = xq + g_tfsq[c+4] - 2.f*acc[i][4];
            o1.y = xq + g_tfsq[c+5] - 2.f*acc[i][5];
            o1.z = xq + g_tfsq[c+6] - 2.f*acc[i][6];
            o1.w = xq + g_tfsq[c+7] - 2.f*acc[i][7];
            *(float4*)&g_Mfeat[(size_t)n*KM + c]     = o0;
            *(float4*)&g_Mfeat[(size_t)n*KM + c + 4] = o1;
        }
    }
}

// ------------------ column-sum partial reduce helper ------------------
__device__ __forceinline__ void colreduce(float* c, float* buf, int tid, float* dst){
    unsigned full = 0xffffffffu;
    #pragma unroll
    for (int j = 0; j < 8; j++){
        c[j] += __shfl_down_sync(full, c[j], 16);
        c[j] += __shfl_down_sync(full, c[j], 8);
    }
    int lane = tid & 31, wp = tid >> 5;
    if (lane < 8){
        #pragma unroll
        for (int j = 0; j < 8; j++) buf[j*256 + wp*8 + lane] = c[j];
    }
    __syncthreads();
    if (tid < 64){
        int j = tid >> 3, kk = tid & 7;
        float s = 0.f;
        #pragma unroll
        for (int w = 0; w < 32; w++) s += buf[j*256 + w*8 + kk];
        __stcg(&dst[kk*8 + j], s);
    }
}

// ---- b-update: vectorized allreduce of Pp (NB x 64) -> sb ----
__device__ __forceinline__ void breduce(const float* Pp, float* buf, float* sb,
                                        const float* sq, int tid){
    int km4 = tid & 15;         // which float4 of the 16 per row
    int r = tid >> 4;           // 0..63
    float4 acc = make_float4(0.f,0.f,0.f,0.f);
    for (int i = r; i < NB; i += 64){
        float4 v = __ldcg((const float4*)&Pp[i*64 + km4*4]);
        acc.x += v.x; acc.y += v.y; acc.z += v.z; acc.w += v.w;
    }
    unsigned full = 0xffffffffu;
    acc.x += __shfl_down_sync(full, acc.x, 16);
    acc.y += __shfl_down_sync(full, acc.y, 16);
    acc.z += __shfl_down_sync(full, acc.z, 16);
    acc.w += __shfl_down_sync(full, acc.w, 16);
    int lane = tid & 31, wp = tid >> 5;
    if (lane < 16) *(float4*)&buf[wp*64 + lane*4] = acc;
    __syncthreads();
    if (tid < 64){
        float s = 0.f;
        #pragma unroll
        for (int w = 0; w < 32; w++) s += buf[w*64 + tid];
        sb[tid] = __fdividef(sq[tid], s);
    }
    __syncthreads();
}

// ---- spmm: CTraw[r][c] = sum_{d in row r} AU[d][c], BLOCK-OWN rows ----
__device__ __forceinline__ void spmm_phase(int B0, int B1, int tid){
    int lane = tid & 31;
    int c2 = lane*2;
    for (int r = B0 + (tid >> 5); r < B1; r += 32){
        int beg = g_rowptr[r], end = g_rowptr[r+1];
        float ax = 0.f, ay = 0.f;
        #pragma unroll 4
        for (int e = beg; e < end; e++){
            int d = g_csrdst[e];
            unsigned uraw = __ldcg((const unsigned*)&g_AU[(size_t)d*KM + c2]);
            float2 u = __bfloat1622float2(*(__nv_bfloat162*)&uraw);
            ax += u.x;
            ay += u.y;
        }
        float2 o = make_float2(ax, ay);
        *(float2*)&g_CT[(size_t)r*KM + c2] = o;
    }
}

// ------------------ the big persistent kernel ------------------
__global__ __launch_bounds__(1024, 1) void k_main(const float* __restrict__ tmpl,
                                                  float* __restrict__ out){
    __shared__ __align__(16) float buf[2048];
    __shared__ float stb[512];
    __shared__ float stsq[64];
    __shared__ float sq[64];
    __shared__ float sb[64];
    __shared__ float sie[8];
    int tid = threadIdx.x;
    int bid = blockIdx.x;
    int gen = 0;
    const float al = g_alpha[0];
    const float om = 1.f - al;

    if (tid < 64){
        sq[tid] = g_q[tid];
        int p = tid >> 3, k2 = tid & 7;
        stsq[p*8 + k2] = g_tsqq[k2*8 + p];
    }

    const int B0 = bid * NPB;
    const int B1 = (B0 + NPB < NN) ? (B0 + NPB) : NN;
    const int k = tid & 7;
    const int nofs = tid >> 3;     // 0..127

    for (int t = 0; t < 5; t++){
        // ---- spmm phase (t>0): block-own rows, no barrier before cost ----
        if (t > 0) spmm_phase(B0, B1, tid);
        // ---- cost phase ----
        if (t == 0){
            if (tid < 64){ int p = tid >> 3, k2 = tid & 7; stb[p*8+k2] = g_tq2[k2*8+p]; }
        } else {
            if (tid < 512){
                int p = tid >> 6, m = (tid >> 3) & 7, k2 = tid & 7;
                stb[tid] = 2.f * sb[k2*8+m] * tmpl[k2*64 + p*8 + m];
            }
        }
        __syncthreads();
        float cabs = 0.f;
        for (int n = B0 + nofs; n < B1; n += 128){
            float d = (float)g_deg[n] * INV_N;
            const float4* mp = (const float4*)&g_Mfeat[(size_t)n*KM + k*8];
            float4 m0 = mp[0], m1 = mp[1];
            float mf[8] = {m0.x,m0.y,m0.z,m0.w,m1.x,m1.y,m1.z,m1.w};
            float cc[8];
            if (t == 0){
                #pragma unroll
                for (int p = 0; p < 8; p++)
                    cc[p] = d + stsq[p*8+k] - d*stb[p*8+k];
            } else {
                const float4* cp0 = (const float4*)&g_CT[(size_t)n*KM + k*8];
                float4 t0 = cp0[0], t1 = cp0[1];
                float ct[8] = {t0.x,t0.y,t0.z,t0.w,t1.x,t1.y,t1.z,t1.w};
                #pragma unroll
                for (int p = 0; p < 8; p++){
                    float s = 0.f;
                    #pragma unroll
                    for (int m = 0; m < 8; m++)
                        s = fmaf(ct[m], stb[p*64 + m*8 + k], s);
                    cc[p] = d + stsq[p*8+k] - s;
                }
            }
            #pragma unroll
            for (int p = 0; p < 8; p++){
                cc[p] = al*cc[p] + om*mf[p];
                cabs += fabsf(cc[p]);
            }
            float4 o0 = make_float4(cc[0],cc[1],cc[2],cc[3]);
            float4 o1 = make_float4(cc[4],cc[5],cc[6],cc[7]);
            float4* cp = (float4*)&g_CT[(size_t)n*KM + k*8];
            cp[0] = o0; cp[1] = o1;
        }
        {
            unsigned full = 0xffffffffu;
            cabs += __shfl_down_sync(full, cabs, 16);
            cabs += __shfl_down_sync(full, cabs, 8);
            int lane = tid & 31, wp = tid >> 5;
            if (lane < 8) buf[wp*8 + lane] = cabs;
            __syncthreads();
            if (tid < 8){
                float s = 0.f;
                #pragma unroll
                for (int w = 0; w < 32; w++) s += buf[w*8 + tid];
                __stcg(&g_Pabs[bid*8 + tid], s);
            }
        }
        gridbar(gen);
        // ---- eps + exp init phase ----
        if (tid < 256){
            int kk = tid & 7, r = tid >> 3;
            float s = 0.f;
            for (int i = r; i < NB; i += 32) s += __ldcg(&g_Pabs[i*8 + kk]);
            buf[tid] = s;
        }
        __syncthreads();
        if (tid < 8){
            float s = 0.f;
            #pragma unroll
            for (int r = 0; r < 32; r++) s += buf[r*8 + tid];
            sie[tid] = (float)(NN*MM) / (EPSREL * s);
        }
        __syncthreads();
        const float ie = sie[k];
        float c[8];
        #pragma unroll
        for (int j = 0; j < 8; j++) c[j] = 0.f;
        for (int n = B0 + nofs; n < B1; n += 128){
            const float4* cp = (const float4*)&g_CT[(size_t)n*KM + k*8];
            float4 c0 = cp[0], c1 = cp[1];
            float u0 = __expf(-c0.x*ie), u1 = __expf(-c0.y*ie);
            float u2 = __expf(-c0.z*ie), u3 = __expf(-c0.w*ie);
            float u4 = __expf(-c1.x*ie), u5 = __expf(-c1.y*ie);
            float u6 = __expf(-c1.z*ie), u7 = __expf(-c1.w*ie);
            __nv_bfloat162 p0 = __floats2bfloat162_rn(u0,u1);
            __nv_bfloat162 p1 = __floats2bfloat162_rn(u2,u3);
            __nv_bfloat162 p2 = __floats2bfloat162_rn(u4,u5);
            __nv_bfloat162 p3 = __floats2bfloat162_rn(u6,u7);
            uint4 raw;
            raw.x = *(unsigned*)&p0; raw.y = *(unsigned*)&p1;
            raw.z = *(unsigned*)&p2; raw.w = *(unsigned*)&p3;
            *(uint4*)&g_Ub[(size_t)n*KM + k*8] = raw;
            float2 v0 = __bfloat1622float2(p0);
            float2 v1 = __bfloat1622float2(p1);
            float2 v2 = __bfloat1622float2(p2);
            float2 v3 = __bfloat1622float2(p3);
            c[0]+=v0.x; c[1]+=v0.y; c[2]+=v1.x; c[3]+=v1.y;
            c[4]+=v2.x; c[5]+=v2.y; c[6]+=v3.x; c[7]+=v3.y;
        }
        colreduce(c, buf, tid, &g_P0[bid*64]);
        gridbar(gen);
        // ---- 20 Sinkhorn iterations (U via L1-cached plain loads) ----
        for (int it = 0; it < 20; it++){
            const float* Pp = (it & 1) ? g_P1 : g_P0;
            float* Pn = (it & 1) ? g_P0 : g_P1;
            breduce(Pp, buf, sb, sq, tid);
            float b0 = sb[k*8+0], b1 = sb[k*8+1], b2 = sb[k*8+2], b3 = sb[k*8+3];
            float b4 = sb[k*8+4], b5 = sb[k*8+5], b6 = sb[k*8+6], b7 = sb[k*8+7];
            if (it < 19){
                #pragma unroll
                for (int j = 0; j < 8; j++) c[j] = 0.f;
                for (int n = B0 + nofs; n < B1; n += 128){
                    uint4 raw = *(const uint4*)&g_Ub[(size_t)n*KM + k*8];
                    float2 u0 = __bfloat1622float2(*(__nv_bfloat162*)&raw.x);
                    float2 u1 = __bfloat1622float2(*(__nv_bfloat162*)&raw.y);
                    float2 u2 = __bfloat1622float2(*(__nv_bfloat162*)&raw.z);
                    float2 u3 = __bfloat1622float2(*(__nv_bfloat162*)&raw.w);
                    float s = b0*u0.x; s = fmaf(b1,u0.y,s);
                    s = fmaf(b2,u1.x,s); s = fmaf(b3,u1.y,s);
                    s = fmaf(b4,u2.x,s); s = fmaf(b5,u2.y,s);
                    s = fmaf(b6,u3.x,s); s = fmaf(b7,u3.y,s);
                    float a = __fdividef(INV_N, s);
                    c[0]=fmaf(a,u0.x,c[0]); c[1]=fmaf(a,u0.y,c[1]);
                    c[2]=fmaf(a,u1.x,c[2]); c[3]=fmaf(a,u1.y,c[3]);
                    c[4]=fmaf(a,u2.x,c[4]); c[5]=fmaf(a,u2.y,c[5]);
                    c[6]=fmaf(a,u3.x,c[6]); c[7]=fmaf(a,u3.y,c[7]);
                }
                colreduce(c, buf, tid, &Pn[bid*64]);
                gridbar(gen);
            } else {
                // final iteration: write AU = a*u (bf16), block-own
                for (int n = B0 + nofs; n < B1; n += 128){
                    uint4 raw = *(const uint4*)&g_Ub[(size_t)n*KM + k*8];
                    float2 u0 = __bfloat1622float2(*(__nv_bfloat162*)&raw.x);
                    float2 u1 = __bfloat1622float2(*(__nv_bfloat162*)&raw.y);
                    float2 u2 = __bfloat1622float2(*(__nv_bfloat162*)&raw.z);
                    float2 u3 = __bfloat1622float2(*(__nv_bfloat162*)&raw.w);
                    float s = b0*u0.x; s = fmaf(b1,u0.y,s);
                    s = fmaf(b2,u1.x,s); s = fmaf(b3,u1.y,s);
                    s = fmaf(b4,u2.x,s); s = fmaf(b5,u2.y,s);
                    s = fmaf(b6,u3.x,s); s = fmaf(b7,u3.y,s);
                    float a = __fdividef(INV_N, s);
                    __nv_bfloat162 q0 = __floats2bfloat162_rn(a*u0.x, a*u0.y);
                    __nv_bfloat162 q1 = __floats2bfloat162_rn(a*u1.x, a*u1.y);
                    __nv_bfloat162 q2 = __floats2bfloat162_rn(a*u2.x, a*u2.y);
                    __nv_bfloat162 q3 = __floats2bfloat162_rn(a*u3.x, a*u3.y);
                    uint4 aw;
                    aw.x = *(unsigned*)&q0; aw.y = *(unsigned*)&q1;
                    aw.z = *(unsigned*)&q2; aw.w = *(unsigned*)&q3;
                    *(uint4*)&g_AU[(size_t)n*KM + k*8] = aw;
                }
            }
        }
        gridbar(gen);   // AU visible for next spmm (cross-block gather)
    }
    // ---- final spmm with converged AU (block-own rows, no barrier) ----
    spmm_phase(B0, B1, tid);
    // ---- fgw partials ----
    if (tid < 512){
        int p = tid >> 6, m = (tid >> 3) & 7, k2 = tid & 7;
        stb[tid] = 2.f * sb[k2*8+m] * tmpl[k2*64 + p*8 + m];
    }
    __syncthreads();
    {
        double s1 = 0.0, s2 = 0.0;
        for (int n = B0 + nofs; n < B1; n += 128){
            float d = (float)g_deg[n] * INV_N;
            uint4 raw = *(const uint4*)&g_AU[(size_t)n*KM + k*8];
            float2 v0 = __bfloat1622float2(*(__nv_bfloat162*)&raw.x);
            float2 v1 = __bfloat1622float2(*(__nv_bfloat162*)&raw.y);
            float2 v2 = __bfloat1622float2(*(__nv_bfloat162*)&raw.z);
            float2 v3 = __bfloat1622float2(*(__nv_bfloat162*)&raw.w);
            float au[8] = {v0.x,v0.y,v1.x,v1.y,v2.x,v2.y,v3.x,v3.y};
            const float4* mp = (const float4*)&g_Mfeat[(size_t)n*KM + k*8];
            float4 m0 = mp[0], m1 = mp[1];
            float mf[8] = {m0.x,m0.y,m0.z,m0.w,m1.x,m1.y,m1.z,m1.w};
            const float4* cp0 = (const float4*)&g_CT[(size_t)n*KM + k*8];
            float4 t0 = cp0[0], t1 = cp0[1];
            float ct[8] = {t0.x,t0.y,t0.z,t0.w,t1.x,t1.y,t1.z,t1.w};
            float accM = 0.f, accT = 0.f;
            #pragma unroll
            for (int p = 0; p < 8; p++){
                float T = au[p] * sb[k*8+p];
                float s = 0.f;
                #pragma unroll
                for (int m = 0; m < 8; m++)
                    s = fmaf(ct[m], stb[p*64 + m*8 + k], s);
                float tens = d + stsq[p*8+k] - s;
                accM = fmaf(mf[p], T, accM);
                accT = fmaf(tens,  T, accT);
            }
            s1 += (double)accM;
            s2 += (double)accT;
        }
        unsigned full = 0xffffffffu;
        s1 += __shfl_down_sync(full, s1, 16);
        s1 += __shfl_down_sync(full, s1, 8);
        s2 += __shfl_down_sync(full, s2, 16);
        s2 += __shfl_down_sync(full, s2, 8);
        double* dbuf = (double*)buf;
        int lane = tid & 31, wp = tid >> 5;
        if (lane < 8){
            dbuf[wp*8 + lane] = s1;
            dbuf[256 + wp*8 + lane] = s2;
        }
        __syncthreads();
        if (tid < 16){
            int which = tid >> 3, k2 = tid & 7;
            double s = 0.0;
            #pragma unroll
            for (int w = 0; w < 32; w++) s += dbuf[which*256 + w*8 + k2];
            g_Fpart[bid*16 + which*8 + k2] = s;
        }
    }
    gridbar(gen);
    // ---- final output (block 0) ----
    if (bid == 0 && tid < 8){
        double sA = 0.0, sB = 0.0;
        for (int i = 0; i < NB; i++){
            sA += __ldcg(&g_Fpart[i*16 + tid]);
            sB += __ldcg(&g_Fpart[i*16 + 8 + tid]);
        }
        double ald = (double)al;
        out[tid] = (float)((1.0 - ald)*sA + ald*sB);
    }
}

// ------------------ launch ------------------
extern "C" void kernel_launch(void* const* d_in, const int* in_sizes, int n_in,
                              void* d_out, int out_size){
    const float* x    = (const float*)d_in[0];
    const int*   ei   = (const int*)  d_in[1];
    const float* tmpl = (const float*)d_in[2];
    const float* tf   = (const float*)d_in[3];
    const float* q0   = (const float*)d_in[4];
    const float* a0   = (const float*)d_in[5];
    float* out = (float*)d_out;
    const int* src = ei;
    const int* dst = ei + NE;

    k_small<<<1, 64>>>(q0, tmpl, tf, a0);
    k_zero<<<NZB, 1024>>>();
    k_hist<<<NEB, 1024>>>(src);
    k_scan1<<<NSC, 1024>>>();
    k_scan2<<<1, 128>>>();
    k_scan3<<<NSC, 1024>>>();
    k_fill<<<NEB, 1024>>>(src, dst);
    k_xsq<<<NSPX, 256>>>(x);
    k_mfeat<<<NMF, 128>>>(x, tf);
    k_main<<<NB, 1024>>>(tmpl, out);
}

// round 17
// speedup vs baseline: 1.1134x; 1.0013x over previous
#include <cuda_runtime.h>
#include <cuda_bf16.h>
#include <math.h>

#define NN 100000
#define NE 1600000
#define FF 128
#define KK 8
#define MM 8
#define KM 64
#define EPSREL 0.05f
#define INV_N 1e-5f

#define NB 148                 /* persistent grid blocks */
#define NPB 676                /* nodes per block */
#define NEB ((NE + 1023)/1024) /* 1563 */
#define NMF ((NN + 127)/128)   /* 782 */
#define NZB ((NN + 1023)/1024) /* 98  */
#define NSPX ((NN + 7)/8)
#define NSC 98

// ------------------ static scratch (no allocations) ------------------
__device__ __align__(128) float g_Mfeat[(size_t)NN*KM];
__device__ __align__(128) __nv_bfloat16 g_Ub[(size_t)NN*KM];  // u (bf16)
__device__ __align__(128) __nv_bfloat16 g_AU[(size_t)NN*KM];  // a*u (bf16)
__device__ __align__(128) float g_CT[(size_t)NN*KM];          // spmm out / cost (fp32)
__device__ __align__(128) float g_xsq[NN];
__device__ __align__(128) float g_P0[NB*KM];
__device__ __align__(128) float g_P1[NB*KM];
__device__ __align__(128) float g_Pabs[NB*KK];
__device__ __align__(128) double g_Fpart[NB*16];
__device__ __align__(128) int   g_deg[NN];
__device__ __align__(128) int   g_rowptr[NN+1];
__device__ __align__(128) int   g_cursor[NN];
__device__ __align__(128) int   g_csrdst[NE];
__device__ __align__(128) int   g_bsum[NSC];
__device__ __align__(128) int   g_boff[NSC];
__device__ float g_q[KM];
__device__ float g_tsqq[KM];
__device__ float g_tq2[KM];
__device__ float g_tfsq[KM];
__device__ float g_alpha[1];
__device__ unsigned g_cnt;

// ---- lightweight release/acquire grid barrier (single counter, R6-proven) ----
__device__ __forceinline__ void gridbar(int &gen){
    __syncthreads();
    if (threadIdx.x == 0){
        unsigned tgt = (unsigned)(gen + 1) * (unsigned)NB;
        asm volatile("red.release.gpu.global.add.u32 [%0], %1;"
                     :: "l"(&g_cnt), "r"(1u) : "memory");
        unsigned v;
        do {
            asm volatile("ld.acquire.gpu.global.u32 %0, [%1];"
                         : "=r"(v) : "l"(&g_cnt) : "memory");
        } while (v < tgt);
    }
    gen++;
    __syncthreads();
}

// ------------------ small precompute (+ counter reset) ------------------
__global__ void k_small(const float* __restrict__ q0, const float* __restrict__ tmpl,
                        const float* __restrict__ tf, const float* __restrict__ a0){
    __shared__ float sq[KM];
    int t = threadIdx.x;  // 64 threads
    if (t == 0) g_cnt = 0u;
    if (t < KM){
        float s = 0.f;
        #pragma unroll 8
        for (int f = 0; f < FF; f++){ float v = tf[t*FF+f]; s = fmaf(v, v, s); }
        g_tfsq[t] = s;
    }
    if (t == 0) g_alpha[0] = 1.f/(1.f + expf(-a0[0]));
    if (t < KK){
        int k = t;
        float mx = -1e30f;
        for (int j = 0; j < MM; j++) mx = fmaxf(mx, q0[k*MM+j]);
        float e[MM]; float s = 0.f;
        for (int j = 0; j < MM; j++){ e[j] = expf(q0[k*MM+j]-mx); s += e[j]; }
        for (int j = 0; j < MM; j++) sq[k*MM+j] = e[j]/s;
    }
    __syncthreads();
    if (t < KM){
        int k = t >> 3, i = t & 7;
        float s = 0.f, s2 = 0.f;
        #pragma unroll
        for (int j = 0; j < MM; j++){
            float tv = tmpl[k*64 + i*8 + j];
            float qv = sq[k*8 + j];
            s  = fmaf(tv*tv, qv, s);
            s2 = fmaf(tv,    qv, s2);
        }
        g_tsqq[t] = s;
        g_tq2[t]  = 2.f*s2;
        g_q[t]    = sq[t];
    }
}

// ------------------ CSR build ------------------
__global__ void k_zero(){
    int i = blockIdx.x*1024 + threadIdx.x;
    if (i < NN) g_deg[i] = 0;
}
__global__ void k_hist(const int* __restrict__ src){
    int e = blockIdx.x*1024 + threadIdx.x;
    if (e < NE) atomicAdd(&g_deg[src[e]], 1);
}
__global__ __launch_bounds__(1024) void k_scan1(){
    __shared__ int ss[1024];
    int t = threadIdx.x;
    int idx = blockIdx.x*1024 + t;
    int v = (idx < NN) ? g_deg[idx] : 0;
    ss[t] = v;
    __syncthreads();
    #pragma unroll
    for (int off = 1; off < 1024; off <<= 1){
        int x = (t >= off) ? ss[t-off] : 0;
        __syncthreads();
        ss[t] += x;
        __syncthreads();
    }
    if (idx < NN) g_rowptr[idx] = ss[t] - v;
    if (t == 1023) g_bsum[blockIdx.x] = ss[t];
}
__global__ void k_scan2(){
    __shared__ int ss[128];
    int t = threadIdx.x;
    int v = (t < NSC) ? g_bsum[t] : 0;
    ss[t] = v;
    __syncthreads();
    #pragma unroll
    for (int off = 1; off < 128; off <<= 1){
        int x = (t >= off) ? ss[t-off] : 0;
        __syncthreads();
        ss[t] += x;
        __syncthreads();
    }
    if (t < NSC) g_boff[t] = ss[t] - v;
    if (t == 0) g_rowptr[NN] = NE;
}
__global__ void k_scan3(){
    int idx = blockIdx.x*1024 + threadIdx.x;
    if (idx < NN){
        int r = g_rowptr[idx] + g_boff[blockIdx.x];
        g_rowptr[idx] = r;
        g_cursor[idx] = r;
    }
}
__global__ void k_fill(const int* __restrict__ src, const int* __restrict__ dst){
    int e = blockIdx.x*1024 + threadIdx.x;
    if (e < NE){
        int s = src[e];
        int pos = atomicAdd(&g_cursor[s], 1);
        g_csrdst[pos] = dst[e];
    }
}

// ------------------ |x|^2 per node ------------------
__global__ __launch_bounds__(256) void k_xsq(const float* __restrict__ x){
    int w = (blockIdx.x*256 + threadIdx.x) >> 5;
    int lane = threadIdx.x & 31;
    if (w >= NN) return;
    float4 v = *(const float4*)&x[(size_t)w*FF + lane*4];
    float s = v.x*v.x + v.y*v.y + v.z*v.z + v.w*v.w;
    #pragma unroll
    for (int o = 16; o > 0; o >>= 1) s += __shfl_down_sync(0xffffffffu, s, o);
    if (lane == 0) g_xsq[w] = s;
}

// ------------------ Mfeat GEMM: 128-node x 64-col tile, 8x8 per thread ------------------
__global__ __launch_bounds__(128) void k_mfeat(const float* __restrict__ x,
                                               const float* __restrict__ tf){
    __shared__ float xs[16][132];
    __shared__ float ts[16][68];
    int tid = threadIdx.x;
    int n0 = blockIdx.x * 128;
    int ty = tid >> 3, tx = tid & 7;
    float acc[8][8];
    #pragma unroll
    for (int i = 0; i < 8; i++)
        #pragma unroll
        for (int j = 0; j < 8; j++) acc[i][j] = 0.f;
    int q = tid & 3, r0 = tid >> 2;
    int rt = tid >> 1, qt = (tid & 1) * 8;
    for (int kb = 0; kb < FF; kb += 16){
        #pragma unroll
        for (int itr = 0; itr < 4; itr++){
            int r = r0 + itr*32;
            int n = n0 + r;
            float4 v = make_float4(0.f,0.f,0.f,0.f);
            if (n < NN) v = *(const float4*)&x[(size_t)n*FF + kb + q*4];
            xs[q*4+0][r] = v.x; xs[q*4+1][r] = v.y;
            xs[q*4+2][r] = v.z; xs[q*4+3][r] = v.w;
        }
        {
            float4 a = *(const float4*)&tf[(size_t)rt*FF + kb + qt];
            float4 b = *(const float4*)&tf[(size_t)rt*FF + kb + qt + 4];
            ts[qt+0][rt] = a.x; ts[qt+1][rt] = a.y; ts[qt+2][rt] = a.z; ts[qt+3][rt] = a.w;
            ts[qt+4][rt] = b.x; ts[qt+5][rt] = b.y; ts[qt+6][rt] = b.z; ts[qt+7][rt] = b.w;
        }
        __syncthreads();
        #pragma unroll
        for (int kk = 0; kk < 16; kk++){
            float4 A0 = *(const float4*)&xs[kk][ty*8];
            float4 A1 = *(const float4*)&xs[kk][ty*8+4];
            float4 B0 = *(const float4*)&ts[kk][tx*8];
            float4 B1 = *(const float4*)&ts[kk][tx*8+4];
            float av[8] = {A0.x,A0.y,A0.z,A0.w,A1.x,A1.y,A1.z,A1.w};
            float bv[8] = {B0.x,B0.y,B0.z,B0.w,B1.x,B1.y,B1.z,B1.w};
            #pragma unroll
            for (int i = 0; i < 8; i++)
                #pragma unroll
                for (int j = 0; j < 8; j++)
                    acc[i][j] = fmaf(av[i], bv[j], acc[i][j]);
        }
        __syncthreads();
    }
    #pragma unroll
    for (int i = 0; i < 8; i++){
        int n = n0 + ty*8 + i;
        if (n < NN){
            float xq = g_xsq[n];
            int c = tx*8;
            float4 o0, o1;
            o0.x = xq + g_tfsq[c+0] - 2.f*acc[i][0];
            o0.y = xq + g_tfsq[c+1] - 2.f*acc[i][1];
            o0.z = xq + g_tfsq[c+2] - 2.f*acc[i][2];
            o0.w = xq + g_tfsq[c+3] - 2.f*acc[i][3];
            o1.x = xq + g_tfsq[c+4] - 2.f*acc[i][4];
            o1.y = xq + g_tfsq[c+5] - 2.f*acc[i][5];
            o1.z = xq + g_tfsq[c+6] - 2.f*acc[i][6];
            o1.w = xq + g_tfsq[c+7] - 2.f*acc[i][7];
            *(float4*)&g_Mfeat[(size_t)n*KM + c]     = o0;
            *(float4*)&g_Mfeat[(size_t)n*KM + c + 4] = o1;
        }
    }
}

// ------------------ column-sum partial reduce (vectorized smem layout) ------------------
// buf layout: [wp*64 + k*8 + j]; dst[k*8+j] = sum_w buf[w*64 + k*8 + j]
__device__ __forceinline__ void colreduce(float* c, float* buf, int tid, float* dst){
    unsigned full = 0xffffffffu;
    #pragma unroll
    for (int j = 0; j < 8; j++){
        c[j] += __shfl_down_sync(full, c[j], 16);
        c[j] += __shfl_down_sync(full, c[j], 8);
    }
    int lane = tid & 31, wp = tid >> 5;
    if (lane < 8){
        float4 lo = make_float4(c[0], c[1], c[2], c[3]);
        float4 hi = make_float4(c[4], c[5], c[6], c[7]);
        *(float4*)&buf[wp*64 + lane*8]     = lo;
        *(float4*)&buf[wp*64 + lane*8 + 4] = hi;
    }
    __syncthreads();
    if (tid < 64){
        float s = 0.f;
        #pragma unroll
        for (int w = 0; w < 32; w++) s += buf[w*64 + tid];
        __stcg(&dst[tid], s);
    }
}

// ---- b-update: vectorized allreduce of Pp (NB x 64) -> sb ----
__device__ __forceinline__ void breduce(const float* Pp, float* buf, float* sb,
                                        const float* sq, int tid){
    int km4 = tid & 15;         // which float4 of the 16 per row
    int r = tid >> 4;           // 0..63
    float4 acc = make_float4(0.f,0.f,0.f,0.f);
    for (int i = r; i < NB; i += 64){
        float4 v = __ldcg((const float4*)&Pp[i*64 + km4*4]);
        acc.x += v.x; acc.y += v.y; acc.z += v.z; acc.w += v.w;
    }
    unsigned full = 0xffffffffu;
    acc.x += __shfl_down_sync(full, acc.x, 16);
    acc.y += __shfl_down_sync(full, acc.y, 16);
    acc.z += __shfl_down_sync(full, acc.z, 16);
    acc.w += __shfl_down_sync(full, acc.w, 16);
    int lane = tid & 31, wp = tid >> 5;
    if (lane < 16) *(float4*)&buf[wp*64 + lane*4] = acc;
    __syncthreads();
    if (tid < 64){
        float s = 0.f;
        #pragma unroll
        for (int w = 0; w < 32; w++) s += buf[w*64 + tid];
        sb[tid] = __fdividef(sq[tid], s);
    }
    __syncthreads();
}

// ---- spmm: CTraw[r][c] = sum_{d in row r} AU[d][c], BLOCK-OWN rows ----
__device__ __forceinline__ void spmm_phase(int B0, int B1, int tid){
    int lane = tid & 31;
    int c2 = lane*2;
    for (int r = B0 + (tid >> 5); r < B1; r += 32){
        int beg = g_rowptr[r], end = g_rowptr[r+1];
        float ax = 0.f, ay = 0.f;
        #pragma unroll 4
        for (int e = beg; e < end; e++){
            int d = g_csrdst[e];
            unsigned uraw = __ldcg((const unsigned*)&g_AU[(size_t)d*KM + c2]);
            float2 u = __bfloat1622float2(*(__nv_bfloat162*)&uraw);
            ax += u.x;
            ay += u.y;
        }
        float2 o = make_float2(ax, ay);
        *(float2*)&g_CT[(size_t)r*KM + c2] = o;
    }
}

// ------------------ the big persistent kernel ------------------
__global__ __launch_bounds__(1024, 1) void k_main(const float* __restrict__ tmpl,
                                                  float* __restrict__ out){
    __shared__ __align__(16) float buf[2048];
    __shared__ float stb[512];
    __shared__ float stsq[64];
    __shared__ float sq[64];
    __shared__ float sb[64];
    __shared__ float sie[8];
    int tid = threadIdx.x;
    int bid = blockIdx.x;
    int gen = 0;
    const float al = g_alpha[0];
    const float om = 1.f - al;

    if (tid < 64){
        sq[tid] = g_q[tid];
        int p = tid >> 3, k2 = tid & 7;
        stsq[p*8 + k2] = g_tsqq[k2*8 + p];
    }

    const int B0 = bid * NPB;
    const int B1 = (B0 + NPB < NN) ? (B0 + NPB) : NN;
    const int k = tid & 7;
    const int nofs = tid >> 3;     // 0..127

    for (int t = 0; t < 5; t++){
        // ---- spmm phase (t>0): block-own rows, no barrier before cost ----
        if (t > 0) spmm_phase(B0, B1, tid);
        // ---- cost phase ----
        if (t == 0){
            if (tid < 64){ int p = tid >> 3, k2 = tid & 7; stb[p*8+k2] = g_tq2[k2*8+p]; }
        } else {
            if (tid < 512){
                int p = tid >> 6, m = (tid >> 3) & 7, k2 = tid & 7;
                stb[tid] = 2.f * sb[k2*8+m] * tmpl[k2*64 + p*8 + m];
            }
        }
        __syncthreads();
        float cabs = 0.f;
        for (int n = B0 + nofs; n < B1; n += 128){
            float d = (float)g_deg[n] * INV_N;
            const float4* mp = (const float4*)&g_Mfeat[(size_t)n*KM + k*8];
            float4 m0 = mp[0], m1 = mp[1];
            float mf[8] = {m0.x,m0.y,m0.z,m0.w,m1.x,m1.y,m1.z,m1.w};
            float cc[8];
            if (t == 0){
                #pragma unroll
                for (int p = 0; p < 8; p++)
                    cc[p] = d + stsq[p*8+k] - d*stb[p*8+k];
            } else {
                const float4* cp0 = (const float4*)&g_CT[(size_t)n*KM + k*8];
                float4 t0 = cp0[0], t1 = cp0[1];
                float ct[8] = {t0.x,t0.y,t0.z,t0.w,t1.x,t1.y,t1.z,t1.w};
                #pragma unroll
                for (int p = 0; p < 8; p++){
                    float s = 0.f;
                    #pragma unroll
                    for (int m = 0; m < 8; m++)
                        s = fmaf(ct[m], stb[p*64 + m*8 + k], s);
                    cc[p] = d + stsq[p*8+k] - s;
                }
            }
            #pragma unroll
            for (int p = 0; p < 8; p++){
                cc[p] = al*cc[p] + om*mf[p];
                cabs += fabsf(cc[p]);
            }
            float4 o0 = make_float4(cc[0],cc[1],cc[2],cc[3]);
            float4 o1 = make_float4(cc[4],cc[5],cc[6],cc[7]);
            float4* cp = (float4*)&g_CT[(size_t)n*KM + k*8];
            cp[0] = o0; cp[1] = o1;
        }
        {
            unsigned full = 0xffffffffu;
            cabs += __shfl_down_sync(full, cabs, 16);
            cabs += __shfl_down_sync(full, cabs, 8);
            int lane = tid & 31, wp = tid >> 5;
            if (lane < 8) buf[wp*8 + lane] = cabs;
            __syncthreads();
            if (tid < 8){
                float s = 0.f;
                #pragma unroll
                for (int w = 0; w < 32; w++) s += buf[w*8 + tid];
                __stcg(&g_Pabs[bid*8 + tid], s);
            }
        }
        gridbar(gen);
        // ---- eps + exp init phase ----
        if (tid < 256){
            int kk = tid & 7, r = tid >> 3;
            float s = 0.f;
            for (int i = r; i < NB; i += 32) s += __ldcg(&g_Pabs[i*8 + kk]);
            buf[tid] = s;
        }
        __syncthreads();
        if (tid < 8){
            float s = 0.f;
            #pragma unroll
            for (int r = 0; r < 32; r++) s += buf[r*8 + tid];
            sie[tid] = (float)(NN*MM) / (EPSREL * s);
        }
        __syncthreads();
        const float ie = sie[k];
        float c[8];
        #pragma unroll
        for (int j = 0; j < 8; j++) c[j] = 0.f;
        for (int n = B0 + nofs; n < B1; n += 128){
            const float4* cp = (const float4*)&g_CT[(size_t)n*KM + k*8];
            float4 c0 = cp[0], c1 = cp[1];
            float u0 = __expf(-c0.x*ie), u1 = __expf(-c0.y*ie);
            float u2 = __expf(-c0.z*ie), u3 = __expf(-c0.w*ie);
            float u4 = __expf(-c1.x*ie), u5 = __expf(-c1.y*ie);
            float u6 = __expf(-c1.z*ie), u7 = __expf(-c1.w*ie);
            __nv_bfloat162 p0 = __floats2bfloat162_rn(u0,u1);
            __nv_bfloat162 p1 = __floats2bfloat162_rn(u2,u3);
            __nv_bfloat162 p2 = __floats2bfloat162_rn(u4,u5);
            __nv_bfloat162 p3 = __floats2bfloat162_rn(u6,u7);
            uint4 raw;
            raw.x = *(unsigned*)&p0; raw.y = *(unsigned*)&p1;
            raw.z = *(unsigned*)&p2; raw.w = *(unsigned*)&p3;
            *(uint4*)&g_Ub[(size_t)n*KM + k*8] = raw;
            float2 v0 = __bfloat1622float2(p0);
            float2 v1 = __bfloat1622float2(p1);
            float2 v2 = __bfloat1622float2(p2);
            float2 v3 = __bfloat1622float2(p3);
            c[0]+=v0.x; c[1]+=v0.y; c[2]+=v1.x; c[3]+=v1.y;
            c[4]+=v2.x; c[5]+=v2.y; c[6]+=v3.x; c[7]+=v3.y;
        }
        colreduce(c, buf, tid, &g_P0[bid*64]);
        gridbar(gen);
        // ---- 20 Sinkhorn iterations (U via L1-cached plain loads) ----
        for (int it = 0; it < 20; it++){
            const float* Pp = (it & 1) ? g_P1 : g_P0;
            float* Pn = (it & 1) ? g_P0 : g_P1;
            breduce(Pp, buf, sb, sq, tid);
            float b0 = sb[k*8+0], b1 = sb[k*8+1], b2 = sb[k*8+2], b3 = sb[k*8+3];
            float b4 = sb[k*8+4], b5 = sb[k*8+5], b6 = sb[k*8+6], b7 = sb[k*8+7];
            if (it < 19){
                #pragma unroll
                for (int j = 0; j < 8; j++) c[j] = 0.f;
                for (int n = B0 + nofs; n < B1; n += 128){
                    uint4 raw = *(const uint4*)&g_Ub[(size_t)n*KM + k*8];
                    float2 u0 = __bfloat1622float2(*(__nv_bfloat162*)&raw.x);
                    float2 u1 = __bfloat1622float2(*(__nv_bfloat162*)&raw.y);
                    float2 u2 = __bfloat1622float2(*(__nv_bfloat162*)&raw.z);
                    float2 u3 = __bfloat1622float2(*(__nv_bfloat162*)&raw.w);
                    float s = b0*u0.x; s = fmaf(b1,u0.y,s);
                    s = fmaf(b2,u1.x,s); s = fmaf(b3,u1.y,s);
                    s = fmaf(b4,u2.x,s); s = fmaf(b5,u2.y,s);
                    s = fmaf(b6,u3.x,s); s = fmaf(b7,u3.y,s);
                    float a = __fdividef(INV_N, s);
                    c[0]=fmaf(a,u0.x,c[0]); c[1]=fmaf(a,u0.y,c[1]);
                    c[2]=fmaf(a,u1.x,c[2]); c[3]=fmaf(a,u1.y,c[3]);
                    c[4]=fmaf(a,u2.x,c[4]); c[5]=fmaf(a,u2.y,c[5]);
                    c[6]=fmaf(a,u3.x,c[6]); c[7]=fmaf(a,u3.y,c[7]);
                }
                colreduce(c, buf, tid, &Pn[bid*64]);
                gridbar(gen);
            } else {
                // final iteration: write AU = a*u (bf16), block-own
                for (int n = B0 + nofs; n < B1; n += 128){
                    uint4 raw = *(const uint4*)&g_Ub[(size_t)n*KM + k*8];
                    float2 u0 = __bfloat1622float2(*(__nv_bfloat162*)&raw.x);
                    float2 u1 = __bfloat1622float2(*(__nv_bfloat162*)&raw.y);
                    float2 u2 = __bfloat1622float2(*(__nv_bfloat162*)&raw.z);
                    float2 u3 = __bfloat1622float2(*(__nv_bfloat162*)&raw.w);
                    float s = b0*u0.x; s = fmaf(b1,u0.y,s);
                    s = fmaf(b2,u1.x,s); s = fmaf(b3,u1.y,s);
                    s = fmaf(b4,u2.x,s); s = fmaf(b5,u2.y,s);
                    s = fmaf(b6,u3.x,s); s = fmaf(b7,u3.y,s);
                    float a = __fdividef(INV_N, s);
                    __nv_bfloat162 q0 = __floats2bfloat162_rn(a*u0.x, a*u0.y);
                    __nv_bfloat162 q1 = __floats2bfloat162_rn(a*u1.x, a*u1.y);
                    __nv_bfloat162 q2 = __floats2bfloat162_rn(a*u2.x, a*u2.y);
                    __nv_bfloat162 q3 = __floats2bfloat162_rn(a*u3.x, a*u3.y);
                    uint4 aw;
                    aw.x = *(unsigned*)&q0; aw.y = *(unsigned*)&q1;
                    aw.z = *(unsigned*)&q2; aw.w = *(unsigned*)&q3;
                    *(uint4*)&g_AU[(size_t)n*KM + k*8] = aw;
                }
            }
        }
        gridbar(gen);   // AU visible for next spmm (cross-block gather)
    }
    // ---- final spmm with converged AU (block-own rows, no barrier) ----
    spmm_phase(B0, B1, tid);
    // ---- fgw partials ----
    if (tid < 512){
        int p = tid >> 6, m = (tid >> 3) & 7, k2 = tid & 7;
        stb[tid] = 2.f * sb[k2*8+m] * tmpl[k2*64 + p*8 + m];
    }
    __syncthreads();
    {
        double s1 = 0.0, s2 = 0.0;
        for (int n = B0 + nofs; n < B1; n += 128){
            float d = (float)g_deg[n] * INV_N;
            uint4 raw = *(const uint4*)&g_AU[(size_t)n*KM + k*8];
            float2 v0 = __bfloat1622float2(*(__nv_bfloat162*)&raw.x);
            float2 v1 = __bfloat1622float2(*(__nv_bfloat162*)&raw.y);
            float2 v2 = __bfloat1622float2(*(__nv_bfloat162*)&raw.z);
            float2 v3 = __bfloat1622float2(*(__nv_bfloat162*)&raw.w);
            float au[8] = {v0.x,v0.y,v1.x,v1.y,v2.x,v2.y,v3.x,v3.y};
            const float4* mp = (const float4*)&g_Mfeat[(size_t)n*KM + k*8];
            float4 m0 = mp[0], m1 = mp[1];
            float mf[8] = {m0.x,m0.y,m0.z,m0.w,m1.x,m1.y,m1.z,m1.w};
            const float4* cp0 = (const float4*)&g_CT[(size_t)n*KM + k*8];
            float4 t0 = cp0[0], t1 = cp0[1];
            float ct[8] = {t0.x,t0.y,t0.z,t0.w,t1.x,t1.y,t1.z,t1.w};
            float accM = 0.f, accT = 0.f;
            #pragma unroll
            for (int p = 0; p < 8; p++){
                float T = au[p] * sb[k*8+p];
                float s = 0.f;
                #pragma unroll
                for (int m = 0; m < 8; m++)
                    s = fmaf(ct[m], stb[p*64 + m*8 + k], s);
                float tens = d + stsq[p*8+k] - s;
                accM = fmaf(mf[p], T, accM);
                accT = fmaf(tens,  T, accT);
            }
            s1 += (double)accM;
            s2 += (double)accT;
        }
        unsigned full = 0xffffffffu;
        s1 += __shfl_down_sync(full, s1, 16);
        s1 += __shfl_down_sync(full, s1, 8);
        s2 += __shfl_down_sync(full, s2, 16);
        s2 += __shfl_down_sync(full, s2, 8);
        double* dbuf = (double*)buf;
        int lane = tid & 31, wp = tid >> 5;
        if (lane < 8){
            dbuf[wp*8 + lane] = s1;
            dbuf[256 + wp*8 + lane] = s2;
        }
        __syncthreads();
        if (tid < 16){
            int which = tid >> 3, k2 = tid & 7;
            double s = 0.0;
            #pragma unroll
            for (int w = 0; w < 32; w++) s += dbuf[which*256 + w*8 + k2];
            g_Fpart[bid*16 + which*8 + k2] = s;
        }
    }
    gridbar(gen);
    // ---- final output (block 0) ----
    if (bid == 0 && tid < 8){
        double sA = 0.0, sB = 0.0;
        for (int i = 0; i < NB; i++){
            sA += __ldcg(&g_Fpart[i*16 + tid]);
            sB += __ldcg(&g_Fpart[i*16 + 8 + tid]);
        }
        double ald = (double)al;
        out[tid] = (float)((1.0 - ald)*sA + ald*sB);
    }
}

// ------------------ launch ------------------
extern "C" void kernel_launch(void* const* d_in, const int* in_sizes, int n_in,
                              void* d_out, int out_size){
    const float* x    = (const float*)d_in[0];
    const int*   ei   = (const int*)  d_in[1];
    const float* tmpl = (const float*)d_in[2];
    const float* tf   = (const float*)d_in[3];
    const float* q0   = (const float*)d_in[4];
    const float* a0   = (const float*)d_in[5];
    float* out = (float*)d_out;
    const int* src = ei;
    const int* dst = ei + NE;

    k_small<<<1, 64>>>(q0, tmpl, tf, a0);
    k_zero<<<NZB, 1024>>>();
    k_hist<<<NEB, 1024>>>(src);
    k_scan1<<<NSC, 1024>>>();
    k_scan2<<<1, 128>>>();
    k_scan3<<<NSC, 1024>>>();
    k_fill<<<NEB, 1024>>>(src, dst);
    k_xsq<<<NSPX, 256>>>(x);
    k_mfeat<<<NMF, 128>>>(x, tf);
    k_main<<<NB, 1024>>>(tmpl, out);
}